// round 1
// baseline (speedup 1.0000x reference)
#include <cuda_runtime.h>
#include <cuda_bf16.h>
#include <math.h>

#define Bc  2
#define Tc  2048
#define Dc  1024
#define NHc 32
#define HDc 32
#define Mc  (Bc*Tc)   // 4096

// Scratch (allocation-free rule: __device__ globals)
__device__ float g_q[Bc*NHc*Tc*HDc];
__device__ float g_k[Bc*NHc*Tc*HDc];
__device__ float g_v[Bc*NHc*Tc*HDc];
__device__ float g_y[Bc*Tc*Dc];

// ---------------------------------------------------------------------------
// Fused QKV GEMM:  out = x @ W^T, epilogue scatters to head-major [B,NH,T,HD]
// C = A(MxK,rm) * B(NxK,rm)^T.  64x64 tile, K-step 16, 256 thr, 4x4 microtile
// ---------------------------------------------------------------------------
__global__ void qkv_gemm(const float* __restrict__ x,
                         const float* __restrict__ Wq,
                         const float* __restrict__ Wk,
                         const float* __restrict__ Wv) {
    __shared__ float As[16][64];
    __shared__ float Bs[16][64];
    const float* W  = (blockIdx.z == 0) ? Wq : (blockIdx.z == 1) ? Wk : Wv;
    float* outp     = (blockIdx.z == 0) ? g_q : (blockIdx.z == 1) ? g_k : g_v;
    const int m0 = blockIdx.y * 64, n0 = blockIdx.x * 64;
    const int tid = threadIdx.x;
    const int ty = tid >> 4, tx = tid & 15;
    const int lrow = tid >> 2, lseg = tid & 3;

    float acc[4][4] = {};
    const float* aptr = x + (m0 + lrow) * Dc + lseg * 4;
    const float* bptr = W + (n0 + lrow) * Dc + lseg * 4;

    for (int k0 = 0; k0 < Dc; k0 += 16) {
        float4 a  = *(const float4*)(aptr + k0);
        float4 bb = *(const float4*)(bptr + k0);
        As[lseg*4+0][lrow] = a.x;  As[lseg*4+1][lrow] = a.y;
        As[lseg*4+2][lrow] = a.z;  As[lseg*4+3][lrow] = a.w;
        Bs[lseg*4+0][lrow] = bb.x; Bs[lseg*4+1][lrow] = bb.y;
        Bs[lseg*4+2][lrow] = bb.z; Bs[lseg*4+3][lrow] = bb.w;
        __syncthreads();
        #pragma unroll
        for (int kk = 0; kk < 16; kk++) {
            float4 av = *(const float4*)&As[kk][ty*4];
            float4 bv = *(const float4*)&Bs[kk][tx*4];
            float ar[4] = {av.x, av.y, av.z, av.w};
            float br[4] = {bv.x, bv.y, bv.z, bv.w};
            #pragma unroll
            for (int i = 0; i < 4; i++)
                #pragma unroll
                for (int j = 0; j < 4; j++)
                    acc[i][j] += ar[i] * br[j];
        }
        __syncthreads();
    }
    #pragma unroll
    for (int i = 0; i < 4; i++) {
        int m = m0 + ty*4 + i;
        int b = m / Tc, t = m % Tc;
        #pragma unroll
        for (int j = 0; j < 4; j++) {
            int n = n0 + tx*4 + j;
            int h = n / HDc, d = n % HDc;
            outp[((b*NHc + h)*Tc + t)*HDc + d] = acc[i][j];
        }
    }
}

// ---------------------------------------------------------------------------
// Per-head RMSNorm + RoPE (+ q_gain). One warp per (b,h,t) row of HD=32.
// blockIdx.y: 0 -> q (with gain), 1 -> k
// ---------------------------------------------------------------------------
__global__ void rope_kernel(const float* __restrict__ cosb,
                            const float* __restrict__ sinb,
                            const float* __restrict__ gain) {
    int r    = blockIdx.x * (blockDim.x >> 5) + (threadIdx.x >> 5);
    int lane = threadIdx.x & 31;
    float* arr = blockIdx.y ? g_k : g_q;
    int t = r % Tc;
    int h = (r / Tc) % NHc;

    float xv = arr[r*HDc + lane];
    float ss = xv * xv;
    #pragma unroll
    for (int o = 16; o; o >>= 1) ss += __shfl_xor_sync(0xffffffffu, ss, o);
    float xr = xv * rsqrtf(ss * (1.0f/HDc) + 1e-6f);
    float xp = __shfl_xor_sync(0xffffffffu, xr, 16);
    int dh = lane & 15;
    float c = cosb[t*(HDc/2) + dh];
    float s = sinb[t*(HDc/2) + dh];
    float out = (lane < 16) ? (xr*c - xp*s) : (xr*c + xp*s);
    if (blockIdx.y == 0) out *= gain[h];
    arr[r*HDc + lane] = out;
}

// ---------------------------------------------------------------------------
// Causal flash attention, fp32. CTA = 64 queries, iterate 64-key blocks.
// 256 threads: (ty,tx) = 16x16; each thread: 4 rows x (4 score cols / 2 out dims)
// ---------------------------------------------------------------------------
__global__ void attn_kernel() {
    __shared__ float Qt[HDc][64];
    __shared__ float Kt[HDc][64];
    __shared__ float Vs[64][HDc];
    __shared__ float Ps[64][64];

    const int bh = blockIdx.y;
    const int q0 = blockIdx.x * 64;
    const float* qp = g_q + (size_t)bh * Tc * HDc;
    const float* kp = g_k + (size_t)bh * Tc * HDc;
    const float* vp = g_v + (size_t)bh * Tc * HDc;
    const int tid = threadIdx.x;
    const int ty = tid >> 4, tx = tid & 15;
    const float scale = 0.17677669529663687f;  // 1/sqrt(32)

    // Load Q block transposed (d-major), pre-scaled
    #pragma unroll
    for (int it = 0; it < 2; it++) {
        int idx = tid + it*256;
        int row = idx >> 3, d4 = idx & 7;
        float4 v = *(const float4*)&qp[(q0+row)*HDc + d4*4];
        Qt[d4*4+0][row] = v.x*scale; Qt[d4*4+1][row] = v.y*scale;
        Qt[d4*4+2][row] = v.z*scale; Qt[d4*4+3][row] = v.w*scale;
    }

    float m_run[4], l_run[4], O[4][2];
    #pragma unroll
    for (int i = 0; i < 4; i++) { m_run[i] = -1e30f; l_run[i] = 0.f; O[i][0] = 0.f; O[i][1] = 0.f; }

    for (int k0 = 0; k0 <= q0; k0 += 64) {
        #pragma unroll
        for (int it = 0; it < 2; it++) {
            int idx = tid + it*256;
            int row = idx >> 3, d4 = idx & 7;
            float4 kv = *(const float4*)&kp[(k0+row)*HDc + d4*4];
            Kt[d4*4+0][row] = kv.x; Kt[d4*4+1][row] = kv.y;
            Kt[d4*4+2][row] = kv.z; Kt[d4*4+3][row] = kv.w;
            float4 vv = *(const float4*)&vp[(k0+row)*HDc + d4*4];
            *(float4*)&Vs[row][d4*4] = vv;
        }
        __syncthreads();

        float s[4][4] = {};
        #pragma unroll
        for (int d = 0; d < HDc; d++) {
            float4 av = *(const float4*)&Qt[d][ty*4];
            float4 bv = *(const float4*)&Kt[d][tx*4];
            float ar[4] = {av.x, av.y, av.z, av.w};
            float br[4] = {bv.x, bv.y, bv.z, bv.w};
            #pragma unroll
            for (int i = 0; i < 4; i++)
                #pragma unroll
                for (int j = 0; j < 4; j++)
                    s[i][j] += ar[i] * br[j];
        }

        if (k0 == q0) {  // diagonal block: causal mask
            #pragma unroll
            for (int i = 0; i < 4; i++)
                #pragma unroll
                for (int j = 0; j < 4; j++)
                    if (k0 + tx*4 + j > q0 + ty*4 + i) s[i][j] = -1e30f;
        }

        // online softmax over this key block (reduce across the 16-lane tx group)
        #pragma unroll
        for (int i = 0; i < 4; i++) {
            float rmax = fmaxf(fmaxf(s[i][0], s[i][1]), fmaxf(s[i][2], s[i][3]));
            #pragma unroll
            for (int o = 8; o; o >>= 1) rmax = fmaxf(rmax, __shfl_xor_sync(0xffffffffu, rmax, o, 16));
            float mn = fmaxf(m_run[i], rmax);
            float corr = __expf(m_run[i] - mn);
            float p0 = __expf(s[i][0]-mn), p1 = __expf(s[i][1]-mn);
            float p2 = __expf(s[i][2]-mn), p3 = __expf(s[i][3]-mn);
            float ps = p0 + p1 + p2 + p3;
            #pragma unroll
            for (int o = 8; o; o >>= 1) ps += __shfl_xor_sync(0xffffffffu, ps, o, 16);
            l_run[i] = l_run[i]*corr + ps;
            m_run[i] = mn;
            O[i][0] *= corr; O[i][1] *= corr;
            float4 pv4 = make_float4(p0, p1, p2, p3);
            *(float4*)&Ps[ty*4+i][tx*4] = pv4;
        }
        __syncthreads();

        // O += P @ V  (each thread: 4 rows x 2 dims)
        #pragma unroll 4
        for (int j = 0; j < 64; j += 4) {
            float2 v0 = *(const float2*)&Vs[j+0][tx*2];
            float2 v1 = *(const float2*)&Vs[j+1][tx*2];
            float2 v2 = *(const float2*)&Vs[j+2][tx*2];
            float2 v3 = *(const float2*)&Vs[j+3][tx*2];
            #pragma unroll
            for (int i = 0; i < 4; i++) {
                float4 p4 = *(const float4*)&Ps[ty*4+i][j];
                O[i][0] += p4.x*v0.x + p4.y*v1.x + p4.z*v2.x + p4.w*v3.x;
                O[i][1] += p4.x*v0.y + p4.y*v1.y + p4.z*v2.y + p4.w*v3.y;
            }
        }
        __syncthreads();
    }

    const int b = bh / NHc, h = bh % NHc;
    #pragma unroll
    for (int i = 0; i < 4; i++) {
        int t = q0 + ty*4 + i;
        float inv = 1.0f / l_run[i];
        float* yp = g_y + (size_t)(b*Tc + t)*Dc + h*HDc + tx*2;
        yp[0] = O[i][0]*inv;
        yp[1] = O[i][1]*inv;
    }
}

// ---------------------------------------------------------------------------
// Output projection: d_out = g_y @ Wproj^T  (plain [M,N] store)
// ---------------------------------------------------------------------------
__global__ void proj_gemm(const float* __restrict__ W, float* __restrict__ out) {
    __shared__ float As[16][64];
    __shared__ float Bs[16][64];
    const int m0 = blockIdx.y * 64, n0 = blockIdx.x * 64;
    const int tid = threadIdx.x;
    const int ty = tid >> 4, tx = tid & 15;
    const int lrow = tid >> 2, lseg = tid & 3;

    float acc[4][4] = {};
    const float* aptr = g_y + (m0 + lrow) * Dc + lseg * 4;
    const float* bptr = W   + (n0 + lrow) * Dc + lseg * 4;

    for (int k0 = 0; k0 < Dc; k0 += 16) {
        float4 a  = *(const float4*)(aptr + k0);
        float4 bb = *(const float4*)(bptr + k0);
        As[lseg*4+0][lrow] = a.x;  As[lseg*4+1][lrow] = a.y;
        As[lseg*4+2][lrow] = a.z;  As[lseg*4+3][lrow] = a.w;
        Bs[lseg*4+0][lrow] = bb.x; Bs[lseg*4+1][lrow] = bb.y;
        Bs[lseg*4+2][lrow] = bb.z; Bs[lseg*4+3][lrow] = bb.w;
        __syncthreads();
        #pragma unroll
        for (int kk = 0; kk < 16; kk++) {
            float4 av = *(const float4*)&As[kk][ty*4];
            float4 bv = *(const float4*)&Bs[kk][tx*4];
            float ar[4] = {av.x, av.y, av.z, av.w};
            float br[4] = {bv.x, bv.y, bv.z, bv.w};
            #pragma unroll
            for (int i = 0; i < 4; i++)
                #pragma unroll
                for (int j = 0; j < 4; j++)
                    acc[i][j] += ar[i] * br[j];
        }
        __syncthreads();
    }
    #pragma unroll
    for (int i = 0; i < 4; i++) {
        int m = m0 + ty*4 + i;
        #pragma unroll
        for (int j = 0; j < 4; j++) {
            int n = n0 + tx*4 + j;
            out[(size_t)m*Dc + n] = acc[i][j];
        }
    }
}

extern "C" void kernel_launch(void* const* d_in, const int* in_sizes, int n_in,
                              void* d_out, int out_size) {
    const float* x    = (const float*)d_in[0];
    const float* Wq   = (const float*)d_in[1];
    const float* Wk   = (const float*)d_in[2];
    const float* Wv   = (const float*)d_in[3];
    const float* Wp   = (const float*)d_in[4];
    const float* gain = (const float*)d_in[5];
    const float* cosb = (const float*)d_in[6];
    const float* sinb = (const float*)d_in[7];

    qkv_gemm<<<dim3(Dc/64, Mc/64, 3), 256>>>(x, Wq, Wk, Wv);
    rope_kernel<<<dim3((Bc*NHc*Tc)/8, 2), 256>>>(cosb, sinb, gain);
    attn_kernel<<<dim3(Tc/64, Bc*NHc), 256>>>();
    proj_gemm<<<dim3(Dc/64, Mc/64), 256>>>(Wp, (float*)d_out);
}

// round 2
// speedup vs baseline: 3.2330x; 3.2330x over previous
#include <cuda_runtime.h>
#include <cuda_bf16.h>
#include <math.h>

#define Bc  2
#define Tc  2048
#define Dc  1024
#define NHc 32
#define HDc 32
#define Mc  (Bc*Tc)   // 4096

// Scratch (allocation-free rule: __device__ globals)
__device__ float g_q[Bc*NHc*Tc*HDc];
__device__ float g_k[Bc*NHc*Tc*HDc];
__device__ float g_v[Bc*NHc*Tc*HDc];
__device__ float g_y[Bc*Tc*Dc];

__device__ __forceinline__ unsigned f2tf(float f) {
    unsigned u;
    asm("cvt.rna.tf32.f32 %0, %1;" : "=r"(u) : "f"(f));
    return u;
}

__device__ __forceinline__ void mma_tf32(float* c, const unsigned* a, const unsigned* b) {
    asm volatile(
        "mma.sync.aligned.m16n8k8.row.col.f32.tf32.tf32.f32 "
        "{%0,%1,%2,%3}, {%4,%5,%6,%7}, {%8,%9}, {%0,%1,%2,%3};"
        : "+f"(c[0]), "+f"(c[1]), "+f"(c[2]), "+f"(c[3])
        : "r"(a[0]), "r"(a[1]), "r"(a[2]), "r"(a[3]), "r"(b[0]), "r"(b[1]));
}

// ---------------------------------------------------------------------------
// tf32 MMA GEMM: C = A(MxK,rm) @ W(NxK,rm)^T. 128x128 tile, Kstep 32, 8 warps.
// MODE 0: scatter to head-major [B,NH,T,HD]; MODE 1: row-major [M,N] out.
// ---------------------------------------------------------------------------
template<int MODE>
__global__ void mma_gemm(const float* __restrict__ A, const float* __restrict__ W,
                         float* __restrict__ out) {
    __shared__ unsigned As[128][36];
    __shared__ unsigned Bs[128][36];
    const int m0 = blockIdx.y * 128, n0 = blockIdx.x * 128;
    const int tid = threadIdx.x, lane = tid & 31, wid = tid >> 5;
    const int wm = wid >> 2, wn = wid & 3;

    float acc[4][4][4] = {};

    for (int k0 = 0; k0 < Dc; k0 += 32) {
        #pragma unroll
        for (int i = 0; i < 4; i++) {
            int idx = tid + i * 256;
            int row = idx >> 3, cg = idx & 7;
            float4 a = *(const float4*)&A[(size_t)(m0 + row) * Dc + k0 + cg * 4];
            As[row][cg*4+0] = f2tf(a.x); As[row][cg*4+1] = f2tf(a.y);
            As[row][cg*4+2] = f2tf(a.z); As[row][cg*4+3] = f2tf(a.w);
            float4 b = *(const float4*)&W[(size_t)(n0 + row) * Dc + k0 + cg * 4];
            Bs[row][cg*4+0] = f2tf(b.x); Bs[row][cg*4+1] = f2tf(b.y);
            Bs[row][cg*4+2] = f2tf(b.z); Bs[row][cg*4+3] = f2tf(b.w);
        }
        __syncthreads();
        #pragma unroll
        for (int kk = 0; kk < 4; kk++) {
            const int kb = kk * 8;
            unsigned af[4][4], bf[4][2];
            #pragma unroll
            for (int mt = 0; mt < 4; mt++) {
                int r = wm*64 + mt*16 + (lane >> 2), c = kb + (lane & 3);
                af[mt][0] = As[r][c];   af[mt][1] = As[r+8][c];
                af[mt][2] = As[r][c+4]; af[mt][3] = As[r+8][c+4];
            }
            #pragma unroll
            for (int nt = 0; nt < 4; nt++) {
                int n = wn*32 + nt*8 + (lane >> 2), c = kb + (lane & 3);
                bf[nt][0] = Bs[n][c]; bf[nt][1] = Bs[n][c+4];
            }
            #pragma unroll
            for (int mt = 0; mt < 4; mt++)
                #pragma unroll
                for (int nt = 0; nt < 4; nt++)
                    mma_tf32(acc[mt][nt], af[mt], bf[nt]);
        }
        __syncthreads();
    }

    #pragma unroll
    for (int mt = 0; mt < 4; mt++) {
        int r0 = m0 + wm*64 + mt*16 + (lane >> 2);
        #pragma unroll
        for (int nt = 0; nt < 4; nt++) {
            int c0 = n0 + wn*32 + nt*8 + (lane & 3)*2;
            if (MODE == 0) {
                int h = c0 >> 5, d = c0 & 31;
                int b = r0 >> 11, t = r0 & 2047;
                float* p = out + (size_t)(((b*NHc + h)*Tc) + t)*HDc + d;
                *(float2*)p = make_float2(acc[mt][nt][0], acc[mt][nt][1]);
                float* p2 = out + (size_t)(((b*NHc + h)*Tc) + t + 8)*HDc + d;
                *(float2*)p2 = make_float2(acc[mt][nt][2], acc[mt][nt][3]);
            } else {
                *(float2*)&out[(size_t)r0*Dc + c0] =
                    make_float2(acc[mt][nt][0], acc[mt][nt][1]);
                *(float2*)&out[(size_t)(r0+8)*Dc + c0] =
                    make_float2(acc[mt][nt][2], acc[mt][nt][3]);
            }
        }
    }
}

// Fused QKV wrapper: blockIdx.z picks (W,out) pair.
__global__ void qkv_gemm(const float* __restrict__ x,
                         const float* __restrict__ Wq,
                         const float* __restrict__ Wk,
                         const float* __restrict__ Wv) {
    __shared__ unsigned As[128][36];
    __shared__ unsigned Bs[128][36];
    const float* W = (blockIdx.z == 0) ? Wq : (blockIdx.z == 1) ? Wk : Wv;
    float* out     = (blockIdx.z == 0) ? g_q : (blockIdx.z == 1) ? g_k : g_v;
    const int m0 = blockIdx.y * 128, n0 = blockIdx.x * 128;
    const int tid = threadIdx.x, lane = tid & 31, wid = tid >> 5;
    const int wm = wid >> 2, wn = wid & 3;

    float acc[4][4][4] = {};

    for (int k0 = 0; k0 < Dc; k0 += 32) {
        #pragma unroll
        for (int i = 0; i < 4; i++) {
            int idx = tid + i * 256;
            int row = idx >> 3, cg = idx & 7;
            float4 a = *(const float4*)&x[(size_t)(m0 + row) * Dc + k0 + cg * 4];
            As[row][cg*4+0] = f2tf(a.x); As[row][cg*4+1] = f2tf(a.y);
            As[row][cg*4+2] = f2tf(a.z); As[row][cg*4+3] = f2tf(a.w);
            float4 b = *(const float4*)&W[(size_t)(n0 + row) * Dc + k0 + cg * 4];
            Bs[row][cg*4+0] = f2tf(b.x); Bs[row][cg*4+1] = f2tf(b.y);
            Bs[row][cg*4+2] = f2tf(b.z); Bs[row][cg*4+3] = f2tf(b.w);
        }
        __syncthreads();
        #pragma unroll
        for (int kk = 0; kk < 4; kk++) {
            const int kb = kk * 8;
            unsigned af[4][4], bf[4][2];
            #pragma unroll
            for (int mt = 0; mt < 4; mt++) {
                int r = wm*64 + mt*16 + (lane >> 2), c = kb + (lane & 3);
                af[mt][0] = As[r][c];   af[mt][1] = As[r+8][c];
                af[mt][2] = As[r][c+4]; af[mt][3] = As[r+8][c+4];
            }
            #pragma unroll
            for (int nt = 0; nt < 4; nt++) {
                int n = wn*32 + nt*8 + (lane >> 2), c = kb + (lane & 3);
                bf[nt][0] = Bs[n][c]; bf[nt][1] = Bs[n][c+4];
            }
            #pragma unroll
            for (int mt = 0; mt < 4; mt++)
                #pragma unroll
                for (int nt = 0; nt < 4; nt++)
                    mma_tf32(acc[mt][nt], af[mt], bf[nt]);
        }
        __syncthreads();
    }

    #pragma unroll
    for (int mt = 0; mt < 4; mt++) {
        int r0 = m0 + wm*64 + mt*16 + (lane >> 2);
        int b = r0 >> 11, t = r0 & 2047;
        #pragma unroll
        for (int nt = 0; nt < 4; nt++) {
            int c0 = n0 + wn*32 + nt*8 + (lane & 3)*2;
            int h = c0 >> 5, d = c0 & 31;
            float* p = out + (size_t)(((b*NHc + h)*Tc) + t)*HDc + d;
            *(float2*)p = make_float2(acc[mt][nt][0], acc[mt][nt][1]);
            float* p2 = out + (size_t)(((b*NHc + h)*Tc) + t + 8)*HDc + d;
            *(float2*)p2 = make_float2(acc[mt][nt][2], acc[mt][nt][3]);
        }
    }
}

// ---------------------------------------------------------------------------
// Per-head RMSNorm + RoPE (+ q_gain). One warp per (b,h,t) row of HD=32.
// ---------------------------------------------------------------------------
__global__ void rope_kernel(const float* __restrict__ cosb,
                            const float* __restrict__ sinb,
                            const float* __restrict__ gain) {
    int r    = blockIdx.x * (blockDim.x >> 5) + (threadIdx.x >> 5);
    int lane = threadIdx.x & 31;
    float* arr = blockIdx.y ? g_k : g_q;
    int t = r % Tc;
    int h = (r / Tc) % NHc;

    float xv = arr[r*HDc + lane];
    float ss = xv * xv;
    #pragma unroll
    for (int o = 16; o; o >>= 1) ss += __shfl_xor_sync(0xffffffffu, ss, o);
    float xr = xv * rsqrtf(ss * (1.0f/HDc) + 1e-6f);
    float xp = __shfl_xor_sync(0xffffffffu, xr, 16);
    int dh = lane & 15;
    float c = cosb[t*(HDc/2) + dh];
    float s = sinb[t*(HDc/2) + dh];
    float out = (lane < 16) ? (xr*c - xp*s) : (xr*c + xp*s);
    if (blockIdx.y == 0) out *= gain[h];
    arr[r*HDc + lane] = out;
}

// ---------------------------------------------------------------------------
// Flash attention with tf32 MMA. CTA: 128 queries, 8 warps (m16 slab each),
// 32-key blocks. Online softmax on C-fragments; P staged via warp-private smem.
// ---------------------------------------------------------------------------
__global__ void attn_mma() {
    __shared__ unsigned Qs[128][36];
    __shared__ unsigned Ks[32][36];
    __shared__ unsigned Vs[32][40];
    __shared__ unsigned Ps[128][36];

    const int bh = blockIdx.y;
    const int q0 = blockIdx.x * 128;
    const float* qp = g_q + (size_t)bh * Tc * HDc;
    const float* kp = g_k + (size_t)bh * Tc * HDc;
    const float* vp = g_v + (size_t)bh * Tc * HDc;
    const int tid = threadIdx.x, lane = tid & 31, wid = tid >> 5;
    const float scale = 0.17677669529663687f;  // 1/sqrt(32)

    // Load Q block (pre-scaled, tf32)
    #pragma unroll
    for (int i = 0; i < 4; i++) {
        int idx = tid + i * 256;
        int row = idx >> 3, cg = idx & 7;
        float4 v = *(const float4*)&qp[(size_t)(q0 + row)*HDc + cg*4];
        Qs[row][cg*4+0] = f2tf(v.x*scale); Qs[row][cg*4+1] = f2tf(v.y*scale);
        Qs[row][cg*4+2] = f2tf(v.z*scale); Qs[row][cg*4+3] = f2tf(v.w*scale);
    }

    float m_run[2] = {-1e30f, -1e30f};
    float l_run[2] = {0.f, 0.f};
    float o[4][4] = {};

    const int lr = wid*16 + (lane >> 2);       // local q-row (first of pair)
    const int gr0 = q0 + lr, gr1 = gr0 + 8;    // global q-rows

    const int nkb = (q0 + 128) / 32;
    for (int kb = 0; kb < nkb; kb++) {
        const int k0 = kb * 32;
        {   // load K,V 32x32 tiles (1 float4 per thread each)
            int row = tid >> 3, cg = tid & 7;
            float4 kv = *(const float4*)&kp[(size_t)(k0 + row)*HDc + cg*4];
            Ks[row][cg*4+0] = f2tf(kv.x); Ks[row][cg*4+1] = f2tf(kv.y);
            Ks[row][cg*4+2] = f2tf(kv.z); Ks[row][cg*4+3] = f2tf(kv.w);
            float4 vv = *(const float4*)&vp[(size_t)(k0 + row)*HDc + cg*4];
            Vs[row][cg*4+0] = f2tf(vv.x); Vs[row][cg*4+1] = f2tf(vv.y);
            Vs[row][cg*4+2] = f2tf(vv.z); Vs[row][cg*4+3] = f2tf(vv.w);
        }
        __syncthreads();

        // S = Q @ K^T for this warp's 16 rows x 32 keys
        float s[4][4] = {};
        #pragma unroll
        for (int kk = 0; kk < 4; kk++) {
            const int cb = kk * 8;
            unsigned af[4], bf[4][2];
            af[0] = Qs[lr][cb + (lane&3)];     af[1] = Qs[lr+8][cb + (lane&3)];
            af[2] = Qs[lr][cb + (lane&3) + 4]; af[3] = Qs[lr+8][cb + (lane&3) + 4];
            #pragma unroll
            for (int nt = 0; nt < 4; nt++) {
                int n = nt*8 + (lane >> 2);
                bf[nt][0] = Ks[n][cb + (lane&3)];
                bf[nt][1] = Ks[n][cb + (lane&3) + 4];
            }
            #pragma unroll
            for (int nt = 0; nt < 4; nt++)
                mma_tf32(s[nt], af, bf[nt]);
        }

        // causal mask (only last 4 key-blocks can clip)
        if (k0 >= q0) {
            #pragma unroll
            for (int nt = 0; nt < 4; nt++) {
                int c0 = k0 + nt*8 + (lane&3)*2;
                if (c0     > gr0) s[nt][0] = -1e30f;
                if (c0 + 1 > gr0) s[nt][1] = -1e30f;
                if (c0     > gr1) s[nt][2] = -1e30f;
                if (c0 + 1 > gr1) s[nt][3] = -1e30f;
            }
        }

        // online softmax, two rows per thread
        #pragma unroll
        for (int r = 0; r < 2; r++) {
            float mx = -1e30f;
            #pragma unroll
            for (int nt = 0; nt < 4; nt++)
                mx = fmaxf(mx, fmaxf(s[nt][2*r], s[nt][2*r+1]));
            mx = fmaxf(mx, __shfl_xor_sync(0xffffffffu, mx, 1));
            mx = fmaxf(mx, __shfl_xor_sync(0xffffffffu, mx, 2));
            float mn = fmaxf(m_run[r], mx);
            float corr = __expf(m_run[r] - mn);
            float sum = 0.f;
            #pragma unroll
            for (int nt = 0; nt < 4; nt++) {
                float p0 = __expf(s[nt][2*r]   - mn);
                float p1 = __expf(s[nt][2*r+1] - mn);
                s[nt][2*r] = p0; s[nt][2*r+1] = p1;
                sum += p0 + p1;
            }
            sum += __shfl_xor_sync(0xffffffffu, sum, 1);
            sum += __shfl_xor_sync(0xffffffffu, sum, 2);
            l_run[r] = l_run[r]*corr + sum;
            m_run[r] = mn;
            #pragma unroll
            for (int nt = 0; nt < 4; nt++) {
                o[nt][2*r]   *= corr;
                o[nt][2*r+1] *= corr;
            }
        }

        // P -> warp-private smem rows (tf32)
        #pragma unroll
        for (int nt = 0; nt < 4; nt++) {
            int c0 = nt*8 + (lane&3)*2;
            Ps[lr][c0]     = f2tf(s[nt][0]);
            Ps[lr][c0+1]   = f2tf(s[nt][1]);
            Ps[lr+8][c0]   = f2tf(s[nt][2]);
            Ps[lr+8][c0+1] = f2tf(s[nt][3]);
        }
        __syncwarp();

        // O += P @ V  (k = 32 keys, n = 32 dims)
        #pragma unroll
        for (int kk = 0; kk < 4; kk++) {
            const int cb = kk * 8;
            unsigned af[4], bf[4][2];
            af[0] = Ps[lr][cb + (lane&3)];     af[1] = Ps[lr+8][cb + (lane&3)];
            af[2] = Ps[lr][cb + (lane&3) + 4]; af[3] = Ps[lr+8][cb + (lane&3) + 4];
            #pragma unroll
            for (int nt = 0; nt < 4; nt++) {
                int n = nt*8 + (lane >> 2);
                bf[nt][0] = Vs[cb + (lane&3)][n];
                bf[nt][1] = Vs[cb + (lane&3) + 4][n];
            }
            #pragma unroll
            for (int nt = 0; nt < 4; nt++)
                mma_tf32(o[nt], af, bf[nt]);
        }
        __syncthreads();
    }

    const int b = bh / NHc, h = bh % NHc;
    const float inv0 = 1.0f / l_run[0];
    const float inv1 = 1.0f / l_run[1];
    #pragma unroll
    for (int nt = 0; nt < 4; nt++) {
        int d = nt*8 + (lane&3)*2;
        float* y0 = g_y + (size_t)(b*Tc + gr0)*Dc + h*HDc + d;
        *(float2*)y0 = make_float2(o[nt][0]*inv0, o[nt][1]*inv0);
        float* y1 = g_y + (size_t)(b*Tc + gr1)*Dc + h*HDc + d;
        *(float2*)y1 = make_float2(o[nt][2]*inv1, o[nt][3]*inv1);
    }
}

extern "C" void kernel_launch(void* const* d_in, const int* in_sizes, int n_in,
                              void* d_out, int out_size) {
    const float* x    = (const float*)d_in[0];
    const float* Wq   = (const float*)d_in[1];
    const float* Wk   = (const float*)d_in[2];
    const float* Wv   = (const float*)d_in[3];
    const float* Wp   = (const float*)d_in[4];
    const float* gain = (const float*)d_in[5];
    const float* cosb = (const float*)d_in[6];
    const float* sinb = (const float*)d_in[7];

    qkv_gemm<<<dim3(Dc/128, Mc/128, 3), 256>>>(x, Wq, Wk, Wv);
    rope_kernel<<<dim3((Bc*NHc*Tc)/8, 2), 256>>>(cosb, sinb, gain);
    attn_mma<<<dim3(Tc/128, Bc*NHc), 256>>>();
    float* yg = nullptr;
    cudaGetSymbolAddress((void**)&yg, g_y);
    mma_gemm<1><<<dim3(Dc/128, Mc/128), 256>>>(yg, Wp, (float*)d_out);
}

// round 4
// speedup vs baseline: 3.5571x; 1.1002x over previous
#include <cuda_runtime.h>
#include <cuda_bf16.h>
#include <math.h>

#define Bc  2
#define Tc  2048
#define Dc  1024
#define NHc 32
#define HDc 32
#define Mc  (Bc*Tc)   // 4096

// Scratch (allocation-free rule: __device__ globals)
__device__ float g_q[Bc*NHc*Tc*HDc];
__device__ float g_k[Bc*NHc*Tc*HDc];
__device__ float g_v[Bc*NHc*Tc*HDc];
__device__ float g_y[Bc*Tc*Dc];

__device__ __forceinline__ unsigned f2tf(float f) {
    unsigned u;
    asm("cvt.rna.tf32.f32 %0, %1;" : "=r"(u) : "f"(f));
    return u;
}

__device__ __forceinline__ void mma_tf32(float* c, const unsigned* a, const unsigned* b) {
    asm volatile(
        "mma.sync.aligned.m16n8k8.row.col.f32.tf32.tf32.f32 "
        "{%0,%1,%2,%3}, {%4,%5,%6,%7}, {%8,%9}, {%0,%1,%2,%3};"
        : "+f"(c[0]), "+f"(c[1]), "+f"(c[2]), "+f"(c[3])
        : "r"(a[0]), "r"(a[1]), "r"(a[2]), "r"(a[3]), "r"(b[0]), "r"(b[1]));
}

__device__ __forceinline__ void cp16(unsigned s, const float* g) {
    asm volatile("cp.async.cg.shared.global [%0], [%1], 16;" :: "r"(s), "l"(g));
}
#define CP_COMMIT()  asm volatile("cp.async.commit_group;")
#define CP_WAIT1()   asm volatile("cp.async.wait_group 1;")
#define CP_WAIT0()   asm volatile("cp.async.wait_group 0;")

// ---------------------------------------------------------------------------
// Fused QKV GEMM + (RMSNorm+RoPE+gain for q,k). 128x128 tile, Kstep 32,
// 2-stage cp.async pipeline, raw fp32 smem, cvt at fragment load.
// ---------------------------------------------------------------------------
__global__ void __launch_bounds__(256, 2)
qkv_fused(const float* __restrict__ x,
          const float* __restrict__ Wq,
          const float* __restrict__ Wk,
          const float* __restrict__ Wv,
          const float* __restrict__ gain,
          const float* __restrict__ cosb,
          const float* __restrict__ sinb) {
    extern __shared__ float sm[];
    float* As = sm;                 // [2][128][36]
    float* Bs = sm + 2*4608;        // [2][128][36]
    const unsigned as_u = (unsigned)__cvta_generic_to_shared(As);
    const unsigned bs_u = (unsigned)__cvta_generic_to_shared(Bs);

    const int z = blockIdx.z;
    const float* W = (z == 0) ? Wq : (z == 1) ? Wk : Wv;
    const int m0 = blockIdx.y * 128, n0 = blockIdx.x * 128;
    const int tid = threadIdx.x, lane = tid & 31, wid = tid >> 5;
    const int wm = wid >> 2, wn = wid & 3;
    const int lrow = tid >> 3, lcg = tid & 7;

    float acc[4][4][4] = {};

    auto load_stage = [&](int buf, int k0) {
        #pragma unroll
        for (int i = 0; i < 4; i++) {
            int row = lrow + i * 32;
            cp16(as_u + (buf*4608 + row*36 + lcg*4)*4,
                 &x[(size_t)(m0 + row)*Dc + k0 + lcg*4]);
            cp16(bs_u + (buf*4608 + row*36 + lcg*4)*4,
                 &W[(size_t)(n0 + row)*Dc + k0 + lcg*4]);
        }
        CP_COMMIT();
    };

    load_stage(0, 0);
    for (int ks = 0; ks < 32; ks++) {
        const int buf = ks & 1;
        if (ks + 1 < 32) { load_stage(buf ^ 1, (ks + 1) * 32); CP_WAIT1(); }
        else             { CP_WAIT0(); }
        __syncthreads();

        const float* fA = As + buf*4608;
        const float* fB = Bs + buf*4608;
        #pragma unroll
        for (int kk = 0; kk < 4; kk++) {
            const int c = kk*8 + (lane & 3);
            unsigned af[4][4], bf[4][2];
            #pragma unroll
            for (int mt = 0; mt < 4; mt++) {
                int r = wm*64 + mt*16 + (lane >> 2);
                af[mt][0] = f2tf(fA[r*36 + c]);       af[mt][1] = f2tf(fA[(r+8)*36 + c]);
                af[mt][2] = f2tf(fA[r*36 + c + 4]);   af[mt][3] = f2tf(fA[(r+8)*36 + c + 4]);
            }
            #pragma unroll
            for (int nt = 0; nt < 4; nt++) {
                int n = wn*32 + nt*8 + (lane >> 2);
                bf[nt][0] = f2tf(fB[n*36 + c]); bf[nt][1] = f2tf(fB[n*36 + c + 4]);
            }
            #pragma unroll
            for (int mt = 0; mt < 4; mt++)
                #pragma unroll
                for (int nt = 0; nt < 4; nt++)
                    mma_tf32(acc[mt][nt], af[mt], bf[nt]);
        }
        __syncthreads();
    }

    // Epilogue. Warp's 32-column slab == one head. h = n0/32 + wn.
    const int h = (n0 >> 5) + wn;
    if (z == 2) {
        #pragma unroll
        for (int mt = 0; mt < 4; mt++) {
            int r0 = m0 + wm*64 + mt*16 + (lane >> 2);
            int b = r0 >> 11, t = r0 & 2047;
            #pragma unroll
            for (int nt = 0; nt < 4; nt++) {
                int d = nt*8 + (lane & 3)*2;
                float* p = g_v + (size_t)(((b*NHc + h)*Tc) + t)*HDc + d;
                *(float2*)p = make_float2(acc[mt][nt][0], acc[mt][nt][1]);
                float* p2 = g_v + (size_t)(((b*NHc + h)*Tc) + t + 8)*HDc + d;
                *(float2*)p2 = make_float2(acc[mt][nt][2], acc[mt][nt][3]);
            }
        }
        return;
    }

    // q/k path: RMSNorm (quad reduce) + RoPE (partner = nt^2) + gain (q only)
    float* out = (z == 0) ? g_q : g_k;
    const float gn = (z == 0) ? gain[h] : 1.0f;
    #pragma unroll
    for (int mt = 0; mt < 4; mt++) {
        int r0 = m0 + wm*64 + mt*16 + (lane >> 2);
        int b = r0 >> 11, t0 = r0 & 2047;

        float ss0 = 0.f, ss1 = 0.f;
        #pragma unroll
        for (int nt = 0; nt < 4; nt++) {
            ss0 += acc[mt][nt][0]*acc[mt][nt][0] + acc[mt][nt][1]*acc[mt][nt][1];
            ss1 += acc[mt][nt][2]*acc[mt][nt][2] + acc[mt][nt][3]*acc[mt][nt][3];
        }
        ss0 += __shfl_xor_sync(0xffffffffu, ss0, 1);
        ss0 += __shfl_xor_sync(0xffffffffu, ss0, 2);
        ss1 += __shfl_xor_sync(0xffffffffu, ss1, 1);
        ss1 += __shfl_xor_sync(0xffffffffu, ss1, 2);
        float sc0 = rsqrtf(ss0 * (1.0f/HDc) + 1e-6f) * gn;
        float sc1 = rsqrtf(ss1 * (1.0f/HDc) + 1e-6f) * gn;

        float nv[4][4];
        #pragma unroll
        for (int nt = 0; nt < 4; nt++) {
            nv[nt][0] = acc[mt][nt][0]*sc0; nv[nt][1] = acc[mt][nt][1]*sc0;
            nv[nt][2] = acc[mt][nt][2]*sc1; nv[nt][3] = acc[mt][nt][3]*sc1;
        }
        #pragma unroll
        for (int nt = 0; nt < 4; nt++) {
            int d  = nt*8 + (lane & 3)*2;      // 0..31 within head
            int dh = d & 15;
            float c00 = cosb[t0*16 + dh],     s00 = sinb[t0*16 + dh];
            float c01 = cosb[t0*16 + dh + 1], s01 = sinb[t0*16 + dh + 1];
            float c10 = cosb[(t0+8)*16 + dh],     s10 = sinb[(t0+8)*16 + dh];
            float c11 = cosb[(t0+8)*16 + dh + 1], s11 = sinb[(t0+8)*16 + dh + 1];
            float o0, o1, o2, o3;
            if (nt < 2) {   // d < 16: x1*c - x2*s
                o0 = nv[nt][0]*c00 - nv[nt^2][0]*s00;
                o1 = nv[nt][1]*c01 - nv[nt^2][1]*s01;
                o2 = nv[nt][2]*c10 - nv[nt^2][2]*s10;
                o3 = nv[nt][3]*c11 - nv[nt^2][3]*s11;
            } else {        // d >= 16: x2*c + x1*s
                o0 = nv[nt][0]*c00 + nv[nt^2][0]*s00;
                o1 = nv[nt][1]*c01 + nv[nt^2][1]*s01;
                o2 = nv[nt][2]*c10 + nv[nt^2][2]*s10;
                o3 = nv[nt][3]*c11 + nv[nt^2][3]*s11;
            }
            float* p = out + (size_t)(((b*NHc + h)*Tc) + t0)*HDc + d;
            *(float2*)p = make_float2(o0, o1);
            float* p2 = out + (size_t)(((b*NHc + h)*Tc) + t0 + 8)*HDc + d;
            *(float2*)p2 = make_float2(o2, o3);
        }
    }
}

// ---------------------------------------------------------------------------
// Output projection: d_out = g_y @ Wproj^T. Same pipelined tf32 MMA GEMM.
// ---------------------------------------------------------------------------
__global__ void __launch_bounds__(256, 2)
proj_gemm(const float* __restrict__ A, const float* __restrict__ W,
          float* __restrict__ out) {
    extern __shared__ float sm[];
    float* As = sm;
    float* Bs = sm + 2*4608;
    const unsigned as_u = (unsigned)__cvta_generic_to_shared(As);
    const unsigned bs_u = (unsigned)__cvta_generic_to_shared(Bs);

    const int m0 = blockIdx.y * 128, n0 = blockIdx.x * 128;
    const int tid = threadIdx.x, lane = tid & 31, wid = tid >> 5;
    const int wm = wid >> 2, wn = wid & 3;
    const int lrow = tid >> 3, lcg = tid & 7;

    float acc[4][4][4] = {};

    auto load_stage = [&](int buf, int k0) {
        #pragma unroll
        for (int i = 0; i < 4; i++) {
            int row = lrow + i * 32;
            cp16(as_u + (buf*4608 + row*36 + lcg*4)*4,
                 &A[(size_t)(m0 + row)*Dc + k0 + lcg*4]);
            cp16(bs_u + (buf*4608 + row*36 + lcg*4)*4,
                 &W[(size_t)(n0 + row)*Dc + k0 + lcg*4]);
        }
        CP_COMMIT();
    };

    load_stage(0, 0);
    for (int ks = 0; ks < 32; ks++) {
        const int buf = ks & 1;
        if (ks + 1 < 32) { load_stage(buf ^ 1, (ks + 1) * 32); CP_WAIT1(); }
        else             { CP_WAIT0(); }
        __syncthreads();

        const float* fA = As + buf*4608;
        const float* fB = Bs + buf*4608;
        #pragma unroll
        for (int kk = 0; kk < 4; kk++) {
            const int c = kk*8 + (lane & 3);
            unsigned af[4][4], bf[4][2];
            #pragma unroll
            for (int mt = 0; mt < 4; mt++) {
                int r = wm*64 + mt*16 + (lane >> 2);
                af[mt][0] = f2tf(fA[r*36 + c]);       af[mt][1] = f2tf(fA[(r+8)*36 + c]);
                af[mt][2] = f2tf(fA[r*36 + c + 4]);   af[mt][3] = f2tf(fA[(r+8)*36 + c + 4]);
            }
            #pragma unroll
            for (int nt = 0; nt < 4; nt++) {
                int n = wn*32 + nt*8 + (lane >> 2);
                bf[nt][0] = f2tf(fB[n*36 + c]); bf[nt][1] = f2tf(fB[n*36 + c + 4]);
            }
            #pragma unroll
            for (int mt = 0; mt < 4; mt++)
                #pragma unroll
                for (int nt = 0; nt < 4; nt++)
                    mma_tf32(acc[mt][nt], af[mt], bf[nt]);
        }
        __syncthreads();
    }

    #pragma unroll
    for (int mt = 0; mt < 4; mt++) {
        int r0 = m0 + wm*64 + mt*16 + (lane >> 2);
        #pragma unroll
        for (int nt = 0; nt < 4; nt++) {
            int c0 = n0 + wn*32 + nt*8 + (lane & 3)*2;
            *(float2*)&out[(size_t)r0*Dc + c0] =
                make_float2(acc[mt][nt][0], acc[mt][nt][1]);
            *(float2*)&out[(size_t)(r0+8)*Dc + c0] =
                make_float2(acc[mt][nt][2], acc[mt][nt][3]);
        }
    }
}

// ---------------------------------------------------------------------------
// Flash attention, tf32 MMA. CTA: 128 q, 8 warps; 64-key blocks with
// cp.async double-buffered K/V.  Ps pitch = 68 (>=64 cols, %32==4).
// ---------------------------------------------------------------------------
#define PS_PITCH 68
__global__ void __launch_bounds__(256, 2)
attn_mma() {
    extern __shared__ float sm[];
    float* Qs = sm;                         // 128 x 36 (scaled fp32)
    float* Ps = sm + 4608;                  // 128 x 68 (tf32 bit patterns)
    float* Ks = Ps + 128*PS_PITCH;          // 2 x 64 x 36
    float* Vs = Ks + 2*2304;                // 2 x 64 x 40
    const unsigned ks_u = (unsigned)__cvta_generic_to_shared(Ks);
    const unsigned vs_u = (unsigned)__cvta_generic_to_shared(Vs);

    const int bh = blockIdx.y;
    const int q0 = blockIdx.x * 128;
    const float* qp = g_q + (size_t)bh * Tc * HDc;
    const float* kp = g_k + (size_t)bh * Tc * HDc;
    const float* vp = g_v + (size_t)bh * Tc * HDc;
    const int tid = threadIdx.x, lane = tid & 31, wid = tid >> 5;
    const float scale = 0.17677669529663687f;  // 1/sqrt(32)

    auto load_kv = [&](int buf, int k0) {
        #pragma unroll
        for (int i = 0; i < 2; i++) {
            int idx = tid + i * 256;
            int row = idx >> 3, cg = idx & 7;
            cp16(ks_u + (buf*2304 + row*36 + cg*4)*4,
                 &kp[(size_t)(k0 + row)*HDc + cg*4]);
            cp16(vs_u + (buf*2560 + row*40 + cg*4)*4,
                 &vp[(size_t)(k0 + row)*HDc + cg*4]);
        }
        CP_COMMIT();
    };

    load_kv(0, 0);

    // Q block, pre-scaled fp32
    #pragma unroll
    for (int i = 0; i < 4; i++) {
        int idx = tid + i * 256;
        int row = idx >> 3, cg = idx & 7;
        float4 v = *(const float4*)&qp[(size_t)(q0 + row)*HDc + cg*4];
        Qs[row*36 + cg*4 + 0] = v.x*scale; Qs[row*36 + cg*4 + 1] = v.y*scale;
        Qs[row*36 + cg*4 + 2] = v.z*scale; Qs[row*36 + cg*4 + 3] = v.w*scale;
    }

    float m_run[2] = {-1e30f, -1e30f};
    float l_run[2] = {0.f, 0.f};
    float o[4][4] = {};

    const int lr = wid*16 + (lane >> 2);
    const int gr0 = q0 + lr, gr1 = gr0 + 8;

    const int nkb = (q0 + 128) / 64;
    for (int kb = 0; kb < nkb; kb++) {
        const int k0 = kb * 64;
        const int buf = kb & 1;
        if (kb + 1 < nkb) { load_kv(buf ^ 1, (kb + 1) * 64); CP_WAIT1(); }
        else              { CP_WAIT0(); }
        __syncthreads();

        const float* fK = Ks + buf*2304;
        const float* fV = Vs + buf*2560;

        // S = Q @ K^T : 16 rows x 64 keys per warp
        float s[8][4] = {};
        #pragma unroll
        for (int kk = 0; kk < 4; kk++) {
            const int c = kk*8 + (lane & 3);
            unsigned af[4], bf[8][2];
            af[0] = f2tf(Qs[lr*36 + c]);       af[1] = f2tf(Qs[(lr+8)*36 + c]);
            af[2] = f2tf(Qs[lr*36 + c + 4]);   af[3] = f2tf(Qs[(lr+8)*36 + c + 4]);
            #pragma unroll
            for (int nt = 0; nt < 8; nt++) {
                int n = nt*8 + (lane >> 2);
                bf[nt][0] = f2tf(fK[n*36 + c]); bf[nt][1] = f2tf(fK[n*36 + c + 4]);
            }
            #pragma unroll
            for (int nt = 0; nt < 8; nt++)
                mma_tf32(s[nt], af, bf[nt]);
        }

        // causal mask
        if (k0 + 63 > q0 + wid*16) {
            #pragma unroll
            for (int nt = 0; nt < 8; nt++) {
                int c0 = k0 + nt*8 + (lane & 3)*2;
                if (c0     > gr0) s[nt][0] = -1e30f;
                if (c0 + 1 > gr0) s[nt][1] = -1e30f;
                if (c0     > gr1) s[nt][2] = -1e30f;
                if (c0 + 1 > gr1) s[nt][3] = -1e30f;
            }
        }

        // online softmax (2 rows/thread)
        #pragma unroll
        for (int r = 0; r < 2; r++) {
            float mx = -1e30f;
            #pragma unroll
            for (int nt = 0; nt < 8; nt++)
                mx = fmaxf(mx, fmaxf(s[nt][2*r], s[nt][2*r+1]));
            mx = fmaxf(mx, __shfl_xor_sync(0xffffffffu, mx, 1));
            mx = fmaxf(mx, __shfl_xor_sync(0xffffffffu, mx, 2));
            float mn = fmaxf(m_run[r], mx);
            float corr = __expf(m_run[r] - mn);
            float sum = 0.f;
            #pragma unroll
            for (int nt = 0; nt < 8; nt++) {
                float p0 = __expf(s[nt][2*r]   - mn);
                float p1 = __expf(s[nt][2*r+1] - mn);
                s[nt][2*r] = p0; s[nt][2*r+1] = p1;
                sum += p0 + p1;
            }
            sum += __shfl_xor_sync(0xffffffffu, sum, 1);
            sum += __shfl_xor_sync(0xffffffffu, sum, 2);
            l_run[r] = l_run[r]*corr + sum;
            m_run[r] = mn;
            #pragma unroll
            for (int nt = 0; nt < 4; nt++) {
                o[nt][2*r]   *= corr;
                o[nt][2*r+1] *= corr;
            }
        }

        // P -> warp-private smem rows (tf32 bits)
        #pragma unroll
        for (int nt = 0; nt < 8; nt++) {
            int c0 = nt*8 + (lane & 3)*2;
            Ps[lr*PS_PITCH + c0]         = __uint_as_float(f2tf(s[nt][0]));
            Ps[lr*PS_PITCH + c0 + 1]     = __uint_as_float(f2tf(s[nt][1]));
            Ps[(lr+8)*PS_PITCH + c0]     = __uint_as_float(f2tf(s[nt][2]));
            Ps[(lr+8)*PS_PITCH + c0 + 1] = __uint_as_float(f2tf(s[nt][3]));
        }
        __syncwarp();

        // O += P @ V (k = 64 keys, n = 32 dims)
        #pragma unroll
        for (int kk = 0; kk < 8; kk++) {
            const int c = kk*8 + (lane & 3);
            unsigned af[4], bf[4][2];
            af[0] = __float_as_uint(Ps[lr*PS_PITCH + c]);
            af[1] = __float_as_uint(Ps[(lr+8)*PS_PITCH + c]);
            af[2] = __float_as_uint(Ps[lr*PS_PITCH + c + 4]);
            af[3] = __float_as_uint(Ps[(lr+8)*PS_PITCH + c + 4]);
            #pragma unroll
            for (int nt = 0; nt < 4; nt++) {
                int n = nt*8 + (lane >> 2);
                bf[nt][0] = f2tf(fV[c*40 + n]);
                bf[nt][1] = f2tf(fV[(c+4)*40 + n]);
            }
            #pragma unroll
            for (int nt = 0; nt < 4; nt++)
                mma_tf32(o[nt], af, bf[nt]);
        }
        __syncthreads();
    }

    const int b = bh / NHc, h = bh % NHc;
    const float inv0 = 1.0f / l_run[0];
    const float inv1 = 1.0f / l_run[1];
    #pragma unroll
    for (int nt = 0; nt < 4; nt++) {
        int d = nt*8 + (lane & 3)*2;
        float* y0 = g_y + (size_t)(b*Tc + gr0)*Dc + h*HDc + d;
        *(float2*)y0 = make_float2(o[nt][0]*inv0, o[nt][1]*inv0);
        float* y1 = g_y + (size_t)(b*Tc + gr1)*Dc + h*HDc + d;
        *(float2*)y1 = make_float2(o[nt][2]*inv1, o[nt][3]*inv1);
    }
}

extern "C" void kernel_launch(void* const* d_in, const int* in_sizes, int n_in,
                              void* d_out, int out_size) {
    const float* x    = (const float*)d_in[0];
    const float* Wq   = (const float*)d_in[1];
    const float* Wk   = (const float*)d_in[2];
    const float* Wv   = (const float*)d_in[3];
    const float* Wp   = (const float*)d_in[4];
    const float* gain = (const float*)d_in[5];
    const float* cosb = (const float*)d_in[6];
    const float* sinb = (const float*)d_in[7];

    const int gemm_smem = 4 * 4608 * 4;                          // 73728 B
    const int attn_smem = (4608 + 128*PS_PITCH + 2*2304 + 2*2560) * 4;  // 92160 B
    cudaFuncSetAttribute(qkv_fused, cudaFuncAttributeMaxDynamicSharedMemorySize, gemm_smem);
    cudaFuncSetAttribute(proj_gemm, cudaFuncAttributeMaxDynamicSharedMemorySize, gemm_smem);
    cudaFuncSetAttribute(attn_mma,  cudaFuncAttributeMaxDynamicSharedMemorySize, attn_smem);

    qkv_fused<<<dim3(Dc/128, Mc/128, 3), 256, gemm_smem>>>(x, Wq, Wk, Wv, gain, cosb, sinb);
    attn_mma<<<dim3(Tc/128, Bc*NHc), 256, attn_smem>>>();
    float* yg = nullptr;
    cudaGetSymbolAddress((void**)&yg, g_y);
    proj_gemm<<<dim3(Dc/128, Mc/128), 256, gemm_smem>>>(yg, Wp, (float*)d_out);
}

// round 5
// speedup vs baseline: 3.6914x; 1.0377x over previous
#include <cuda_runtime.h>
#include <cuda_bf16.h>
#include <math.h>

#define Bc  2
#define Tc  2048
#define Dc  1024
#define NHc 32
#define HDc 32
#define Mc  (Bc*Tc)   // 4096

// Scratch (allocation-free rule: __device__ globals). All hold tf32 bit patterns
// stored as float, except g_y-consumers read them as tf32 operands directly.
__device__ float g_xt[Mc*Dc];      // x,  tf32
__device__ float g_wqt[Dc*Dc];     // Wq, tf32
__device__ float g_wkt[Dc*Dc];     // Wk, tf32
__device__ float g_wvt[Dc*Dc];     // Wv, tf32
__device__ float g_wpt[Dc*Dc];     // Wproj, tf32
__device__ float g_q[Bc*NHc*Tc*HDc];   // post rope*gain*scale, tf32 bits
__device__ float g_k[Bc*NHc*Tc*HDc];   // post rope, tf32 bits
__device__ float g_v[Bc*NHc*Tc*HDc];   // tf32 bits
__device__ float g_y[Bc*Tc*Dc];        // attn out, tf32 bits

__device__ __forceinline__ unsigned f2tf(float f) {
    unsigned u;
    asm("cvt.rna.tf32.f32 %0, %1;" : "=r"(u) : "f"(f));
    return u;
}

__device__ __forceinline__ void mma_tf32(float* c, const unsigned* a, const unsigned* b) {
    asm volatile(
        "mma.sync.aligned.m16n8k8.row.col.f32.tf32.tf32.f32 "
        "{%0,%1,%2,%3}, {%4,%5,%6,%7}, {%8,%9}, {%0,%1,%2,%3};"
        : "+f"(c[0]), "+f"(c[1]), "+f"(c[2]), "+f"(c[3])
        : "r"(a[0]), "r"(a[1]), "r"(a[2]), "r"(a[3]), "r"(b[0]), "r"(b[1]));
}

__device__ __forceinline__ void cp16(unsigned s, const float* g) {
    asm volatile("cp.async.cg.shared.global [%0], [%1], 16;" :: "r"(s), "l"(g));
}
#define CP_COMMIT()  asm volatile("cp.async.commit_group;")
#define CP_WAIT1()   asm volatile("cp.async.wait_group 1;")
#define CP_WAIT0()   asm volatile("cp.async.wait_group 0;")

// ---------------------------------------------------------------------------
// Prepass: round x + 4 weights to tf32 bit patterns (one RNA per element).
// ---------------------------------------------------------------------------
__global__ void prep_tf32(const float* __restrict__ x,  const float* __restrict__ wq,
                          const float* __restrict__ wk, const float* __restrict__ wv,
                          const float* __restrict__ wp) {
    const long NX = (long)Mc*Dc/4;      // 1M float4
    const long NW = (long)Dc*Dc/4;      // 256K float4
    long i = (long)blockIdx.x*blockDim.x + threadIdx.x;
    if (i >= NX + 4*NW) return;
    const float4* s; float4* d;
    if (i < NX) { s = (const float4*)x + i; d = (float4*)g_xt + i; }
    else {
        long j = i - NX; int w = (int)(j / NW); long o = j % NW;
        const float* sw = (w == 0) ? wq : (w == 1) ? wk : (w == 2) ? wv : wp;
        float* dw = (w == 0) ? g_wqt : (w == 1) ? g_wkt : (w == 2) ? g_wvt : g_wpt;
        s = (const float4*)sw + o; d = (float4*)dw + o;
    }
    float4 v = *s;
    *d = make_float4(__uint_as_float(f2tf(v.x)), __uint_as_float(f2tf(v.y)),
                     __uint_as_float(f2tf(v.z)), __uint_as_float(f2tf(v.w)));
}

// ---------------------------------------------------------------------------
// Fused QKV GEMM + (RMSNorm+RoPE+gain+scale for q, RMSNorm+RoPE for k).
// 128x128 tile, Kstep 32, 2-stage cp.async pipeline. Operands already tf32.
// ---------------------------------------------------------------------------
__global__ void __launch_bounds__(256, 2)
qkv_fused(const float* __restrict__ gain,
          const float* __restrict__ cosb,
          const float* __restrict__ sinb) {
    extern __shared__ float sm[];
    float* As = sm;                 // [2][128][36]
    float* Bs = sm + 2*4608;        // [2][128][36]
    const unsigned as_u = (unsigned)__cvta_generic_to_shared(As);
    const unsigned bs_u = (unsigned)__cvta_generic_to_shared(Bs);

    const int z = blockIdx.z;
    const float* W = (z == 0) ? g_wqt : (z == 1) ? g_wkt : g_wvt;
    const int m0 = blockIdx.y * 128, n0 = blockIdx.x * 128;
    const int tid = threadIdx.x, lane = tid & 31, wid = tid >> 5;
    const int wm = wid >> 2, wn = wid & 3;
    const int lrow = tid >> 3, lcg = tid & 7;

    float acc[4][4][4] = {};

    auto load_stage = [&](int buf, int k0) {
        #pragma unroll
        for (int i = 0; i < 4; i++) {
            int row = lrow + i * 32;
            cp16(as_u + (buf*4608 + row*36 + lcg*4)*4,
                 &g_xt[(size_t)(m0 + row)*Dc + k0 + lcg*4]);
            cp16(bs_u + (buf*4608 + row*36 + lcg*4)*4,
                 &W[(size_t)(n0 + row)*Dc + k0 + lcg*4]);
        }
        CP_COMMIT();
    };

    load_stage(0, 0);
    for (int ks = 0; ks < 32; ks++) {
        const int buf = ks & 1;
        if (ks + 1 < 32) { load_stage(buf ^ 1, (ks + 1) * 32); CP_WAIT1(); }
        else             { CP_WAIT0(); }
        __syncthreads();

        const float* fA = As + buf*4608;
        const float* fB = Bs + buf*4608;
        #pragma unroll
        for (int kk = 0; kk < 4; kk++) {
            const int c = kk*8 + (lane & 3);
            unsigned af[4][4], bf[4][2];
            #pragma unroll
            for (int mt = 0; mt < 4; mt++) {
                int r = wm*64 + mt*16 + (lane >> 2);
                af[mt][0] = __float_as_uint(fA[r*36 + c]);
                af[mt][1] = __float_as_uint(fA[(r+8)*36 + c]);
                af[mt][2] = __float_as_uint(fA[r*36 + c + 4]);
                af[mt][3] = __float_as_uint(fA[(r+8)*36 + c + 4]);
            }
            #pragma unroll
            for (int nt = 0; nt < 4; nt++) {
                int n = wn*32 + nt*8 + (lane >> 2);
                bf[nt][0] = __float_as_uint(fB[n*36 + c]);
                bf[nt][1] = __float_as_uint(fB[n*36 + c + 4]);
            }
            #pragma unroll
            for (int mt = 0; mt < 4; mt++)
                #pragma unroll
                for (int nt = 0; nt < 4; nt++)
                    mma_tf32(acc[mt][nt], af[mt], bf[nt]);
        }
        __syncthreads();
    }

    // Epilogue. Warp's 32-column slab == one head. h = n0/32 + wn.
    const int h = (n0 >> 5) + wn;
    if (z == 2) {
        #pragma unroll
        for (int mt = 0; mt < 4; mt++) {
            int r0 = m0 + wm*64 + mt*16 + (lane >> 2);
            int b = r0 >> 11, t = r0 & 2047;
            #pragma unroll
            for (int nt = 0; nt < 4; nt++) {
                int d = nt*8 + (lane & 3)*2;
                float* p = g_v + (size_t)(((b*NHc + h)*Tc) + t)*HDc + d;
                *(float2*)p = make_float2(__uint_as_float(f2tf(acc[mt][nt][0])),
                                          __uint_as_float(f2tf(acc[mt][nt][1])));
                float* p2 = g_v + (size_t)(((b*NHc + h)*Tc) + t + 8)*HDc + d;
                *(float2*)p2 = make_float2(__uint_as_float(f2tf(acc[mt][nt][2])),
                                           __uint_as_float(f2tf(acc[mt][nt][3])));
            }
        }
        return;
    }

    // q/k path: RMSNorm (quad reduce) + RoPE (partner = nt^2) + gain*scale (q)
    float* out = (z == 0) ? g_q : g_k;
    const float gn = (z == 0) ? gain[h] * 0.17677669529663687f : 1.0f;
    #pragma unroll
    for (int mt = 0; mt < 4; mt++) {
        int r0 = m0 + wm*64 + mt*16 + (lane >> 2);
        int b = r0 >> 11, t0 = r0 & 2047;

        float ss0 = 0.f, ss1 = 0.f;
        #pragma unroll
        for (int nt = 0; nt < 4; nt++) {
            ss0 += acc[mt][nt][0]*acc[mt][nt][0] + acc[mt][nt][1]*acc[mt][nt][1];
            ss1 += acc[mt][nt][2]*acc[mt][nt][2] + acc[mt][nt][3]*acc[mt][nt][3];
        }
        ss0 += __shfl_xor_sync(0xffffffffu, ss0, 1);
        ss0 += __shfl_xor_sync(0xffffffffu, ss0, 2);
        ss1 += __shfl_xor_sync(0xffffffffu, ss1, 1);
        ss1 += __shfl_xor_sync(0xffffffffu, ss1, 2);
        float sc0 = rsqrtf(ss0 * (1.0f/HDc) + 1e-6f) * gn;
        float sc1 = rsqrtf(ss1 * (1.0f/HDc) + 1e-6f) * gn;

        float nv[4][4];
        #pragma unroll
        for (int nt = 0; nt < 4; nt++) {
            nv[nt][0] = acc[mt][nt][0]*sc0; nv[nt][1] = acc[mt][nt][1]*sc0;
            nv[nt][2] = acc[mt][nt][2]*sc1; nv[nt][3] = acc[mt][nt][3]*sc1;
        }
        #pragma unroll
        for (int nt = 0; nt < 4; nt++) {
            int d  = nt*8 + (lane & 3)*2;      // 0..31 within head
            int dh = d & 15;
            float c00 = cosb[t0*16 + dh],     s00 = sinb[t0*16 + dh];
            float c01 = cosb[t0*16 + dh + 1], s01 = sinb[t0*16 + dh + 1];
            float c10 = cosb[(t0+8)*16 + dh],     s10 = sinb[(t0+8)*16 + dh];
            float c11 = cosb[(t0+8)*16 + dh + 1], s11 = sinb[(t0+8)*16 + dh + 1];
            float o0, o1, o2, o3;
            if (nt < 2) {   // d < 16: x1*c - x2*s
                o0 = nv[nt][0]*c00 - nv[nt^2][0]*s00;
                o1 = nv[nt][1]*c01 - nv[nt^2][1]*s01;
                o2 = nv[nt][2]*c10 - nv[nt^2][2]*s10;
                o3 = nv[nt][3]*c11 - nv[nt^2][3]*s11;
            } else {        // d >= 16: x2*c + x1*s
                o0 = nv[nt][0]*c00 + nv[nt^2][0]*s00;
                o1 = nv[nt][1]*c01 + nv[nt^2][1]*s01;
                o2 = nv[nt][2]*c10 + nv[nt^2][2]*s10;
                o3 = nv[nt][3]*c11 + nv[nt^2][3]*s11;
            }
            float* p = out + (size_t)(((b*NHc + h)*Tc) + t0)*HDc + d;
            *(float2*)p = make_float2(__uint_as_float(f2tf(o0)),
                                      __uint_as_float(f2tf(o1)));
            float* p2 = out + (size_t)(((b*NHc + h)*Tc) + t0 + 8)*HDc + d;
            *(float2*)p2 = make_float2(__uint_as_float(f2tf(o2)),
                                       __uint_as_float(f2tf(o3)));
        }
    }
}

// ---------------------------------------------------------------------------
// Output projection: d_out = g_y @ Wproj^T (both already tf32). fp32 out.
// ---------------------------------------------------------------------------
__global__ void __launch_bounds__(256, 2)
proj_gemm(float* __restrict__ out) {
    extern __shared__ float sm[];
    float* As = sm;
    float* Bs = sm + 2*4608;
    const unsigned as_u = (unsigned)__cvta_generic_to_shared(As);
    const unsigned bs_u = (unsigned)__cvta_generic_to_shared(Bs);

    const int m0 = blockIdx.y * 128, n0 = blockIdx.x * 128;
    const int tid = threadIdx.x, lane = tid & 31, wid = tid >> 5;
    const int wm = wid >> 2, wn = wid & 3;
    const int lrow = tid >> 3, lcg = tid & 7;

    float acc[4][4][4] = {};

    auto load_stage = [&](int buf, int k0) {
        #pragma unroll
        for (int i = 0; i < 4; i++) {
            int row = lrow + i * 32;
            cp16(as_u + (buf*4608 + row*36 + lcg*4)*4,
                 &g_y[(size_t)(m0 + row)*Dc + k0 + lcg*4]);
            cp16(bs_u + (buf*4608 + row*36 + lcg*4)*4,
                 &g_wpt[(size_t)(n0 + row)*Dc + k0 + lcg*4]);
        }
        CP_COMMIT();
    };

    load_stage(0, 0);
    for (int ks = 0; ks < 32; ks++) {
        const int buf = ks & 1;
        if (ks + 1 < 32) { load_stage(buf ^ 1, (ks + 1) * 32); CP_WAIT1(); }
        else             { CP_WAIT0(); }
        __syncthreads();

        const float* fA = As + buf*4608;
        const float* fB = Bs + buf*4608;
        #pragma unroll
        for (int kk = 0; kk < 4; kk++) {
            const int c = kk*8 + (lane & 3);
            unsigned af[4][4], bf[4][2];
            #pragma unroll
            for (int mt = 0; mt < 4; mt++) {
                int r = wm*64 + mt*16 + (lane >> 2);
                af[mt][0] = __float_as_uint(fA[r*36 + c]);
                af[mt][1] = __float_as_uint(fA[(r+8)*36 + c]);
                af[mt][2] = __float_as_uint(fA[r*36 + c + 4]);
                af[mt][3] = __float_as_uint(fA[(r+8)*36 + c + 4]);
            }
            #pragma unroll
            for (int nt = 0; nt < 4; nt++) {
                int n = wn*32 + nt*8 + (lane >> 2);
                bf[nt][0] = __float_as_uint(fB[n*36 + c]);
                bf[nt][1] = __float_as_uint(fB[n*36 + c + 4]);
            }
            #pragma unroll
            for (int mt = 0; mt < 4; mt++)
                #pragma unroll
                for (int nt = 0; nt < 4; nt++)
                    mma_tf32(acc[mt][nt], af[mt], bf[nt]);
        }
        __syncthreads();
    }

    #pragma unroll
    for (int mt = 0; mt < 4; mt++) {
        int r0 = m0 + wm*64 + mt*16 + (lane >> 2);
        #pragma unroll
        for (int nt = 0; nt < 4; nt++) {
            int c0 = n0 + wn*32 + nt*8 + (lane & 3)*2;
            *(float2*)&out[(size_t)r0*Dc + c0] =
                make_float2(acc[mt][nt][0], acc[mt][nt][1]);
            *(float2*)&out[(size_t)(r0+8)*Dc + c0] =
                make_float2(acc[mt][nt][2], acc[mt][nt][3]);
        }
    }
}

// ---------------------------------------------------------------------------
// Flash attention, tf32 MMA. CTA: 128 q, 8 warps; 64-key blocks, cp.async
// double-buffered K/V. All operands pre-rounded tf32 — no cvt in hot loop
// except P after exp.  Ps pitch = 68.
// ---------------------------------------------------------------------------
#define PS_PITCH 68
__global__ void __launch_bounds__(256, 2)
attn_mma() {
    extern __shared__ float sm[];
    float* Qs = sm;                         // 128 x 36 (tf32 bits, pre-scaled)
    float* Ps = sm + 4608;                  // 128 x 68 (tf32 bits)
    float* Ks = Ps + 128*PS_PITCH;          // 2 x 64 x 36
    float* Vs = Ks + 2*2304;                // 2 x 64 x 40
    const unsigned ks_u = (unsigned)__cvta_generic_to_shared(Ks);
    const unsigned vs_u = (unsigned)__cvta_generic_to_shared(Vs);

    const int bh = blockIdx.y;
    const int q0 = blockIdx.x * 128;
    const float* qp = g_q + (size_t)bh * Tc * HDc;
    const float* kp = g_k + (size_t)bh * Tc * HDc;
    const float* vp = g_v + (size_t)bh * Tc * HDc;
    const int tid = threadIdx.x, lane = tid & 31, wid = tid >> 5;

    auto load_kv = [&](int buf, int k0) {
        #pragma unroll
        for (int i = 0; i < 2; i++) {
            int idx = tid + i * 256;
            int row = idx >> 3, cg = idx & 7;
            cp16(ks_u + (buf*2304 + row*36 + cg*4)*4,
                 &kp[(size_t)(k0 + row)*HDc + cg*4]);
            cp16(vs_u + (buf*2560 + row*40 + cg*4)*4,
                 &vp[(size_t)(k0 + row)*HDc + cg*4]);
        }
        CP_COMMIT();
    };

    load_kv(0, 0);

    // Q block (already tf32 bits, pre-scaled by gain/sqrt(hd))
    #pragma unroll
    for (int i = 0; i < 4; i++) {
        int idx = tid + i * 256;
        int row = idx >> 3, cg = idx & 7;
        float4 v = *(const float4*)&qp[(size_t)(q0 + row)*HDc + cg*4];
        *(float4*)&Qs[row*36 + cg*4] = v;
    }

    float m_run[2] = {-1e30f, -1e30f};
    float l_run[2] = {0.f, 0.f};
    float o[4][4] = {};

    const int lr = wid*16 + (lane >> 2);
    const int gr0 = q0 + lr, gr1 = gr0 + 8;

    const int nkb = (q0 + 128) / 64;
    for (int kb = 0; kb < nkb; kb++) {
        const int k0 = kb * 64;
        const int buf = kb & 1;
        if (kb + 1 < nkb) { load_kv(buf ^ 1, (kb + 1) * 64); CP_WAIT1(); }
        else              { CP_WAIT0(); }
        __syncthreads();

        const float* fK = Ks + buf*2304;
        const float* fV = Vs + buf*2560;

        // S = Q @ K^T : 16 rows x 64 keys per warp
        float s[8][4] = {};
        #pragma unroll
        for (int kk = 0; kk < 4; kk++) {
            const int c = kk*8 + (lane & 3);
            unsigned af[4], bf[8][2];
            af[0] = __float_as_uint(Qs[lr*36 + c]);
            af[1] = __float_as_uint(Qs[(lr+8)*36 + c]);
            af[2] = __float_as_uint(Qs[lr*36 + c + 4]);
            af[3] = __float_as_uint(Qs[(lr+8)*36 + c + 4]);
            #pragma unroll
            for (int nt = 0; nt < 8; nt++) {
                int n = nt*8 + (lane >> 2);
                bf[nt][0] = __float_as_uint(fK[n*36 + c]);
                bf[nt][1] = __float_as_uint(fK[n*36 + c + 4]);
            }
            #pragma unroll
            for (int nt = 0; nt < 8; nt++)
                mma_tf32(s[nt], af, bf[nt]);
        }

        // causal mask
        if (k0 + 63 > q0 + wid*16) {
            #pragma unroll
            for (int nt = 0; nt < 8; nt++) {
                int c0 = k0 + nt*8 + (lane & 3)*2;
                if (c0     > gr0) s[nt][0] = -1e30f;
                if (c0 + 1 > gr0) s[nt][1] = -1e30f;
                if (c0     > gr1) s[nt][2] = -1e30f;
                if (c0 + 1 > gr1) s[nt][3] = -1e30f;
            }
        }

        // online softmax (2 rows/thread)
        #pragma unroll
        for (int r = 0; r < 2; r++) {
            float mx = -1e30f;
            #pragma unroll
            for (int nt = 0; nt < 8; nt++)
                mx = fmaxf(mx, fmaxf(s[nt][2*r], s[nt][2*r+1]));
            mx = fmaxf(mx, __shfl_xor_sync(0xffffffffu, mx, 1));
            mx = fmaxf(mx, __shfl_xor_sync(0xffffffffu, mx, 2));
            float mn = fmaxf(m_run[r], mx);
            float corr = __expf(m_run[r] - mn);
            float sum = 0.f;
            #pragma unroll
            for (int nt = 0; nt < 8; nt++) {
                float p0 = __expf(s[nt][2*r]   - mn);
                float p1 = __expf(s[nt][2*r+1] - mn);
                s[nt][2*r] = p0; s[nt][2*r+1] = p1;
                sum += p0 + p1;
            }
            sum += __shfl_xor_sync(0xffffffffu, sum, 1);
            sum += __shfl_xor_sync(0xffffffffu, sum, 2);
            l_run[r] = l_run[r]*corr + sum;
            m_run[r] = mn;
            #pragma unroll
            for (int nt = 0; nt < 4; nt++) {
                o[nt][2*r]   *= corr;
                o[nt][2*r+1] *= corr;
            }
        }

        // P -> warp-private smem rows (tf32 bits)
        #pragma unroll
        for (int nt = 0; nt < 8; nt++) {
            int c0 = nt*8 + (lane & 3)*2;
            Ps[lr*PS_PITCH + c0]         = __uint_as_float(f2tf(s[nt][0]));
            Ps[lr*PS_PITCH + c0 + 1]     = __uint_as_float(f2tf(s[nt][1]));
            Ps[(lr+8)*PS_PITCH + c0]     = __uint_as_float(f2tf(s[nt][2]));
            Ps[(lr+8)*PS_PITCH + c0 + 1] = __uint_as_float(f2tf(s[nt][3]));
        }
        __syncwarp();

        // O += P @ V (k = 64 keys, n = 32 dims)
        #pragma unroll
        for (int kk = 0; kk < 8; kk++) {
            const int c = kk*8 + (lane & 3);
            unsigned af[4], bf[4][2];
            af[0] = __float_as_uint(Ps[lr*PS_PITCH + c]);
            af[1] = __float_as_uint(Ps[(lr+8)*PS_PITCH + c]);
            af[2] = __float_as_uint(Ps[lr*PS_PITCH + c + 4]);
            af[3] = __float_as_uint(Ps[(lr+8)*PS_PITCH + c + 4]);
            #pragma unroll
            for (int nt = 0; nt < 4; nt++) {
                int n = nt*8 + (lane >> 2);
                bf[nt][0] = __float_as_uint(fV[c*40 + n]);
                bf[nt][1] = __float_as_uint(fV[(c+4)*40 + n]);
            }
            #pragma unroll
            for (int nt = 0; nt < 4; nt++)
                mma_tf32(o[nt], af, bf[nt]);
        }
        __syncthreads();
    }

    const int b = bh / NHc, h = bh % NHc;
    const float inv0 = 1.0f / l_run[0];
    const float inv1 = 1.0f / l_run[1];
    #pragma unroll
    for (int nt = 0; nt < 4; nt++) {
        int d = nt*8 + (lane & 3)*2;
        float* y0 = g_y + (size_t)(b*Tc + gr0)*Dc + h*HDc + d;
        *(float2*)y0 = make_float2(__uint_as_float(f2tf(o[nt][0]*inv0)),
                                   __uint_as_float(f2tf(o[nt][1]*inv0)));
        float* y1 = g_y + (size_t)(b*Tc + gr1)*Dc + h*HDc + d;
        *(float2*)y1 = make_float2(__uint_as_float(f2tf(o[nt][2]*inv1)),
                                   __uint_as_float(f2tf(o[nt][3]*inv1)));
    }
}

extern "C" void kernel_launch(void* const* d_in, const int* in_sizes, int n_in,
                              void* d_out, int out_size) {
    const float* x    = (const float*)d_in[0];
    const float* Wq   = (const float*)d_in[1];
    const float* Wk   = (const float*)d_in[2];
    const float* Wv   = (const float*)d_in[3];
    const float* Wp   = (const float*)d_in[4];
    const float* gain = (const float*)d_in[5];
    const float* cosb = (const float*)d_in[6];
    const float* sinb = (const float*)d_in[7];

    const int gemm_smem = 4 * 4608 * 4;                          // 73728 B
    const int attn_smem = (4608 + 128*PS_PITCH + 2*2304 + 2*2560) * 4;  // 92160 B
    cudaFuncSetAttribute(qkv_fused, cudaFuncAttributeMaxDynamicSharedMemorySize, gemm_smem);
    cudaFuncSetAttribute(proj_gemm, cudaFuncAttributeMaxDynamicSharedMemorySize, gemm_smem);
    cudaFuncSetAttribute(attn_mma,  cudaFuncAttributeMaxDynamicSharedMemorySize, attn_smem);

    const long nprep = (long)Mc*Dc/4 + 4L*Dc*Dc/4;   // 2M float4
    prep_tf32<<<(int)((nprep + 255)/256), 256>>>(x, Wq, Wk, Wv, Wp);
    qkv_fused<<<dim3(Dc/128, Mc/128, 3), 256, gemm_smem>>>(gain, cosb, sinb);
    attn_mma<<<dim3(Tc/128, Bc*NHc), 256, attn_smem>>>();
    proj_gemm<<<dim3(Dc/128, Mc/128), 256, gemm_smem>>>((float*)d_out);
}

// round 6
// speedup vs baseline: 3.8579x; 1.0451x over previous
#include <cuda_runtime.h>
#include <cuda_bf16.h>
#include <math.h>

#define Bc  2
#define Tc  2048
#define Dc  1024
#define NHc 32
#define HDc 32
#define Mc  (Bc*Tc)   // 4096

// Scratch (allocation-free rule: __device__ globals). tf32 bit patterns.
__device__ float g_xt[Mc*Dc];
__device__ float g_wqt[Dc*Dc];
__device__ float g_wkt[Dc*Dc];
__device__ float g_wvt[Dc*Dc];
__device__ float g_wpt[Dc*Dc];
__device__ float g_q[Bc*NHc*Tc*HDc];   // post rope*gain*scale*log2e, tf32
__device__ float g_k[Bc*NHc*Tc*HDc];   // post rope, tf32
__device__ float g_v[Bc*NHc*Tc*HDc];   // tf32
__device__ float g_y[Bc*Tc*Dc];        // attn out, tf32

__device__ __forceinline__ unsigned f2tf(float f) {
    unsigned u;
    asm("cvt.rna.tf32.f32 %0, %1;" : "=r"(u) : "f"(f));
    return u;
}

__device__ __forceinline__ void mma_tf32(float* c, const unsigned* a, const unsigned* b) {
    asm volatile(
        "mma.sync.aligned.m16n8k8.row.col.f32.tf32.tf32.f32 "
        "{%0,%1,%2,%3}, {%4,%5,%6,%7}, {%8,%9}, {%0,%1,%2,%3};"
        : "+f"(c[0]), "+f"(c[1]), "+f"(c[2]), "+f"(c[3])
        : "r"(a[0]), "r"(a[1]), "r"(a[2]), "r"(a[3]), "r"(b[0]), "r"(b[1]));
}

__device__ __forceinline__ void cp16(unsigned s, const float* g) {
    asm volatile("cp.async.cg.shared.global [%0], [%1], 16;" :: "r"(s), "l"(g));
}
#define CP_COMMIT()  asm volatile("cp.async.commit_group;")
#define CP_WAIT1()   asm volatile("cp.async.wait_group 1;")
#define CP_WAIT0()   asm volatile("cp.async.wait_group 0;")

// ---------------------------------------------------------------------------
// Prepass: round x + 4 weights to tf32 (one RNA per element).
// ---------------------------------------------------------------------------
__global__ void prep_tf32(const float* __restrict__ x,  const float* __restrict__ wq,
                          const float* __restrict__ wk, const float* __restrict__ wv,
                          const float* __restrict__ wp) {
    const long NX = (long)Mc*Dc/4;
    const long NW = (long)Dc*Dc/4;
    long i = (long)blockIdx.x*blockDim.x + threadIdx.x;
    if (i >= NX + 4*NW) return;
    const float4* s; float4* d;
    if (i < NX) { s = (const float4*)x + i; d = (float4*)g_xt + i; }
    else {
        long j = i - NX; int w = (int)(j / NW); long o = j % NW;
        const float* sw = (w == 0) ? wq : (w == 1) ? wk : (w == 2) ? wv : wp;
        float* dw = (w == 0) ? g_wqt : (w == 1) ? g_wkt : (w == 2) ? g_wvt : g_wpt;
        s = (const float4*)sw + o; d = (float4*)dw + o;
    }
    float4 v = *s;
    *d = make_float4(__uint_as_float(f2tf(v.x)), __uint_as_float(f2tf(v.y)),
                     __uint_as_float(f2tf(v.z)), __uint_as_float(f2tf(v.w)));
}

// ---------------------------------------------------------------------------
// Fused QKV GEMM + (RMSNorm+RoPE+gain for q/k). 128x128 tile, Kstep 32,
// 3-stage cp.async pipeline, single __syncthreads per K-step.
// ---------------------------------------------------------------------------
__global__ void __launch_bounds__(256, 2)
qkv_fused(const float* __restrict__ gain,
          const float* __restrict__ cosb,
          const float* __restrict__ sinb) {
    extern __shared__ float sm[];
    float* As = sm;                 // [3][128][36]
    float* Bs = sm + 3*4608;        // [3][128][36]
    const unsigned as_u = (unsigned)__cvta_generic_to_shared(As);
    const unsigned bs_u = (unsigned)__cvta_generic_to_shared(Bs);

    const int z = blockIdx.z;
    const float* W = (z == 0) ? g_wqt : (z == 1) ? g_wkt : g_wvt;
    const int m0 = blockIdx.y * 128, n0 = blockIdx.x * 128;
    const int tid = threadIdx.x, lane = tid & 31, wid = tid >> 5;
    const int wm = wid >> 2, wn = wid & 3;
    const int lrow = tid >> 3, lcg = tid & 7;

    float acc[4][4][4] = {};

    auto load_stage = [&](int buf, int k0) {
        #pragma unroll
        for (int i = 0; i < 4; i++) {
            int row = lrow + i * 32;
            cp16(as_u + (buf*4608 + row*36 + lcg*4)*4,
                 &g_xt[(size_t)(m0 + row)*Dc + k0 + lcg*4]);
            cp16(bs_u + (buf*4608 + row*36 + lcg*4)*4,
                 &W[(size_t)(n0 + row)*Dc + k0 + lcg*4]);
        }
        CP_COMMIT();
    };

    load_stage(0, 0);
    load_stage(1, 32);
    int buf = 0;
    for (int ks = 0; ks < 32; ks++) {
        if (ks == 31) { CP_WAIT0(); } else { CP_WAIT1(); }
        __syncthreads();
        if (ks + 2 < 32) {
            int nb = buf + 2; if (nb >= 3) nb -= 3;
            load_stage(nb, (ks + 2) * 32);
        }

        const float* fA = As + buf*4608;
        const float* fB = Bs + buf*4608;
        #pragma unroll
        for (int kk = 0; kk < 4; kk++) {
            const int c = kk*8 + (lane & 3);
            unsigned af[4][4], bf[4][2];
            #pragma unroll
            for (int mt = 0; mt < 4; mt++) {
                int r = wm*64 + mt*16 + (lane >> 2);
                af[mt][0] = __float_as_uint(fA[r*36 + c]);
                af[mt][1] = __float_as_uint(fA[(r+8)*36 + c]);
                af[mt][2] = __float_as_uint(fA[r*36 + c + 4]);
                af[mt][3] = __float_as_uint(fA[(r+8)*36 + c + 4]);
            }
            #pragma unroll
            for (int nt = 0; nt < 4; nt++) {
                int n = wn*32 + nt*8 + (lane >> 2);
                bf[nt][0] = __float_as_uint(fB[n*36 + c]);
                bf[nt][1] = __float_as_uint(fB[n*36 + c + 4]);
            }
            #pragma unroll
            for (int mt = 0; mt < 4; mt++)
                #pragma unroll
                for (int nt = 0; nt < 4; nt++)
                    mma_tf32(acc[mt][nt], af[mt], bf[nt]);
        }
        if (++buf >= 3) buf = 0;
    }

    // Epilogue. Warp's 32-column slab == one head. h = n0/32 + wn.
    const int h = (n0 >> 5) + wn;
    if (z == 2) {
        #pragma unroll
        for (int mt = 0; mt < 4; mt++) {
            int r0 = m0 + wm*64 + mt*16 + (lane >> 2);
            int b = r0 >> 11, t = r0 & 2047;
            #pragma unroll
            for (int nt = 0; nt < 4; nt++) {
                int d = nt*8 + (lane & 3)*2;
                float* p = g_v + (size_t)(((b*NHc + h)*Tc) + t)*HDc + d;
                *(float2*)p = make_float2(__uint_as_float(f2tf(acc[mt][nt][0])),
                                          __uint_as_float(f2tf(acc[mt][nt][1])));
                float* p2 = g_v + (size_t)(((b*NHc + h)*Tc) + t + 8)*HDc + d;
                *(float2*)p2 = make_float2(__uint_as_float(f2tf(acc[mt][nt][2])),
                                           __uint_as_float(f2tf(acc[mt][nt][3])));
            }
        }
        return;
    }

    // q/k: RMSNorm (quad reduce) + RoPE (partner = nt^2).
    // q additionally scaled by gain * 1/sqrt(hd) * log2(e)  (exp2 softmax).
    float* out = (z == 0) ? g_q : g_k;
    const float gn = (z == 0)
        ? gain[h] * 0.17677669529663687f * 1.4426950408889634f : 1.0f;
    #pragma unroll
    for (int mt = 0; mt < 4; mt++) {
        int r0 = m0 + wm*64 + mt*16 + (lane >> 2);
        int b = r0 >> 11, t0 = r0 & 2047;

        float ss0 = 0.f, ss1 = 0.f;
        #pragma unroll
        for (int nt = 0; nt < 4; nt++) {
            ss0 += acc[mt][nt][0]*acc[mt][nt][0] + acc[mt][nt][1]*acc[mt][nt][1];
            ss1 += acc[mt][nt][2]*acc[mt][nt][2] + acc[mt][nt][3]*acc[mt][nt][3];
        }
        ss0 += __shfl_xor_sync(0xffffffffu, ss0, 1);
        ss0 += __shfl_xor_sync(0xffffffffu, ss0, 2);
        ss1 += __shfl_xor_sync(0xffffffffu, ss1, 1);
        ss1 += __shfl_xor_sync(0xffffffffu, ss1, 2);
        float sc0 = rsqrtf(ss0 * (1.0f/HDc) + 1e-6f) * gn;
        float sc1 = rsqrtf(ss1 * (1.0f/HDc) + 1e-6f) * gn;

        float nv[4][4];
        #pragma unroll
        for (int nt = 0; nt < 4; nt++) {
            nv[nt][0] = acc[mt][nt][0]*sc0; nv[nt][1] = acc[mt][nt][1]*sc0;
            nv[nt][2] = acc[mt][nt][2]*sc1; nv[nt][3] = acc[mt][nt][3]*sc1;
        }
        #pragma unroll
        for (int nt = 0; nt < 4; nt++) {
            int d  = nt*8 + (lane & 3)*2;
            int dh = d & 15;
            float c00 = cosb[t0*16 + dh],     s00 = sinb[t0*16 + dh];
            float c01 = cosb[t0*16 + dh + 1], s01 = sinb[t0*16 + dh + 1];
            float c10 = cosb[(t0+8)*16 + dh],     s10 = sinb[(t0+8)*16 + dh];
            float c11 = cosb[(t0+8)*16 + dh + 1], s11 = sinb[(t0+8)*16 + dh + 1];
            float o0, o1, o2, o3;
            if (nt < 2) {
                o0 = nv[nt][0]*c00 - nv[nt^2][0]*s00;
                o1 = nv[nt][1]*c01 - nv[nt^2][1]*s01;
                o2 = nv[nt][2]*c10 - nv[nt^2][2]*s10;
                o3 = nv[nt][3]*c11 - nv[nt^2][3]*s11;
            } else {
                o0 = nv[nt][0]*c00 + nv[nt^2][0]*s00;
                o1 = nv[nt][1]*c01 + nv[nt^2][1]*s01;
                o2 = nv[nt][2]*c10 + nv[nt^2][2]*s10;
                o3 = nv[nt][3]*c11 + nv[nt^2][3]*s11;
            }
            float* p = out + (size_t)(((b*NHc + h)*Tc) + t0)*HDc + d;
            *(float2*)p = make_float2(__uint_as_float(f2tf(o0)),
                                      __uint_as_float(f2tf(o1)));
            float* p2 = out + (size_t)(((b*NHc + h)*Tc) + t0 + 8)*HDc + d;
            *(float2*)p2 = make_float2(__uint_as_float(f2tf(o2)),
                                       __uint_as_float(f2tf(o3)));
        }
    }
}

// ---------------------------------------------------------------------------
// Output projection: d_out = g_y @ Wproj^T. 3-stage pipeline.
// ---------------------------------------------------------------------------
__global__ void __launch_bounds__(256, 2)
proj_gemm(float* __restrict__ out) {
    extern __shared__ float sm[];
    float* As = sm;
    float* Bs = sm + 3*4608;
    const unsigned as_u = (unsigned)__cvta_generic_to_shared(As);
    const unsigned bs_u = (unsigned)__cvta_generic_to_shared(Bs);

    const int m0 = blockIdx.y * 128, n0 = blockIdx.x * 128;
    const int tid = threadIdx.x, lane = tid & 31, wid = tid >> 5;
    const int wm = wid >> 2, wn = wid & 3;
    const int lrow = tid >> 3, lcg = tid & 7;

    float acc[4][4][4] = {};

    auto load_stage = [&](int buf, int k0) {
        #pragma unroll
        for (int i = 0; i < 4; i++) {
            int row = lrow + i * 32;
            cp16(as_u + (buf*4608 + row*36 + lcg*4)*4,
                 &g_y[(size_t)(m0 + row)*Dc + k0 + lcg*4]);
            cp16(bs_u + (buf*4608 + row*36 + lcg*4)*4,
                 &g_wpt[(size_t)(n0 + row)*Dc + k0 + lcg*4]);
        }
        CP_COMMIT();
    };

    load_stage(0, 0);
    load_stage(1, 32);
    int buf = 0;
    for (int ks = 0; ks < 32; ks++) {
        if (ks == 31) { CP_WAIT0(); } else { CP_WAIT1(); }
        __syncthreads();
        if (ks + 2 < 32) {
            int nb = buf + 2; if (nb >= 3) nb -= 3;
            load_stage(nb, (ks + 2) * 32);
        }

        const float* fA = As + buf*4608;
        const float* fB = Bs + buf*4608;
        #pragma unroll
        for (int kk = 0; kk < 4; kk++) {
            const int c = kk*8 + (lane & 3);
            unsigned af[4][4], bf[4][2];
            #pragma unroll
            for (int mt = 0; mt < 4; mt++) {
                int r = wm*64 + mt*16 + (lane >> 2);
                af[mt][0] = __float_as_uint(fA[r*36 + c]);
                af[mt][1] = __float_as_uint(fA[(r+8)*36 + c]);
                af[mt][2] = __float_as_uint(fA[r*36 + c + 4]);
                af[mt][3] = __float_as_uint(fA[(r+8)*36 + c + 4]);
            }
            #pragma unroll
            for (int nt = 0; nt < 4; nt++) {
                int n = wn*32 + nt*8 + (lane >> 2);
                bf[nt][0] = __float_as_uint(fB[n*36 + c]);
                bf[nt][1] = __float_as_uint(fB[n*36 + c + 4]);
            }
            #pragma unroll
            for (int mt = 0; mt < 4; mt++)
                #pragma unroll
                for (int nt = 0; nt < 4; nt++)
                    mma_tf32(acc[mt][nt], af[mt], bf[nt]);
        }
        if (++buf >= 3) buf = 0;
    }

    #pragma unroll
    for (int mt = 0; mt < 4; mt++) {
        int r0 = m0 + wm*64 + mt*16 + (lane >> 2);
        #pragma unroll
        for (int nt = 0; nt < 4; nt++) {
            int c0 = n0 + wn*32 + nt*8 + (lane & 3)*2;
            *(float2*)&out[(size_t)r0*Dc + c0] =
                make_float2(acc[mt][nt][0], acc[mt][nt][1]);
            *(float2*)&out[(size_t)(r0+8)*Dc + c0] =
                make_float2(acc[mt][nt][2], acc[mt][nt][3]);
        }
    }
}

// ---------------------------------------------------------------------------
// Flash attention, tf32 MMA, exp2-softmax (log2e folded into q).
// CTA: 128 q, 8 warps; 64-key blocks, 2-stage cp.async K/V.
// P written raw fp32 (HW truncates to tf32), float2 stores.
// ---------------------------------------------------------------------------
#define PS_PITCH 68
__global__ void __launch_bounds__(256, 2)
attn_mma() {
    extern __shared__ float sm[];
    float* Qs = sm;                         // 128 x 36
    float* Ps = sm + 4608;                  // 128 x 68
    float* Ks = Ps + 128*PS_PITCH;          // 2 x 64 x 36
    float* Vs = Ks + 2*2304;                // 2 x 64 x 40
    const unsigned ks_u = (unsigned)__cvta_generic_to_shared(Ks);
    const unsigned vs_u = (unsigned)__cvta_generic_to_shared(Vs);

    const int bh = blockIdx.y;
    const int q0 = blockIdx.x * 128;
    const float* qp = g_q + (size_t)bh * Tc * HDc;
    const float* kp = g_k + (size_t)bh * Tc * HDc;
    const float* vp = g_v + (size_t)bh * Tc * HDc;
    const int tid = threadIdx.x, lane = tid & 31, wid = tid >> 5;

    auto load_kv = [&](int buf, int k0) {
        #pragma unroll
        for (int i = 0; i < 2; i++) {
            int idx = tid + i * 256;
            int row = idx >> 3, cg = idx & 7;
            cp16(ks_u + (buf*2304 + row*36 + cg*4)*4,
                 &kp[(size_t)(k0 + row)*HDc + cg*4]);
            cp16(vs_u + (buf*2560 + row*40 + cg*4)*4,
                 &vp[(size_t)(k0 + row)*HDc + cg*4]);
        }
        CP_COMMIT();
    };

    load_kv(0, 0);

    #pragma unroll
    for (int i = 0; i < 4; i++) {
        int idx = tid + i * 256;
        int row = idx >> 3, cg = idx & 7;
        float4 v = *(const float4*)&qp[(size_t)(q0 + row)*HDc + cg*4];
        *(float4*)&Qs[row*36 + cg*4] = v;
    }

    float m_run[2] = {-1e30f, -1e30f};
    float l_run[2] = {0.f, 0.f};
    float o[4][4] = {};

    const int lr = wid*16 + (lane >> 2);
    const int gr0 = q0 + lr, gr1 = gr0 + 8;

    const int nkb = (q0 + 128) / 64;
    for (int kb = 0; kb < nkb; kb++) {
        const int k0 = kb * 64;
        const int buf = kb & 1;
        if (kb + 1 < nkb) { load_kv(buf ^ 1, (kb + 1) * 64); CP_WAIT1(); }
        else              { CP_WAIT0(); }
        __syncthreads();

        const float* fK = Ks + buf*2304;
        const float* fV = Vs + buf*2560;

        float s[8][4] = {};
        #pragma unroll
        for (int kk = 0; kk < 4; kk++) {
            const int c = kk*8 + (lane & 3);
            unsigned af[4], bf[8][2];
            af[0] = __float_as_uint(Qs[lr*36 + c]);
            af[1] = __float_as_uint(Qs[(lr+8)*36 + c]);
            af[2] = __float_as_uint(Qs[lr*36 + c + 4]);
            af[3] = __float_as_uint(Qs[(lr+8)*36 + c + 4]);
            #pragma unroll
            for (int nt = 0; nt < 8; nt++) {
                int n = nt*8 + (lane >> 2);
                bf[nt][0] = __float_as_uint(fK[n*36 + c]);
                bf[nt][1] = __float_as_uint(fK[n*36 + c + 4]);
            }
            #pragma unroll
            for (int nt = 0; nt < 8; nt++)
                mma_tf32(s[nt], af, bf[nt]);
        }

        if (k0 + 63 > q0 + wid*16) {
            #pragma unroll
            for (int nt = 0; nt < 8; nt++) {
                int c0 = k0 + nt*8 + (lane & 3)*2;
                if (c0     > gr0) s[nt][0] = -1e30f;
                if (c0 + 1 > gr0) s[nt][1] = -1e30f;
                if (c0     > gr1) s[nt][2] = -1e30f;
                if (c0 + 1 > gr1) s[nt][3] = -1e30f;
            }
        }

        // online softmax, base-2 (scores already scaled by log2e)
        #pragma unroll
        for (int r = 0; r < 2; r++) {
            float mx = -1e30f;
            #pragma unroll
            for (int nt = 0; nt < 8; nt++)
                mx = fmaxf(mx, fmaxf(s[nt][2*r], s[nt][2*r+1]));
            mx = fmaxf(mx, __shfl_xor_sync(0xffffffffu, mx, 1));
            mx = fmaxf(mx, __shfl_xor_sync(0xffffffffu, mx, 2));
            float mn = fmaxf(m_run[r], mx);
            float corr = exp2f(m_run[r] - mn);
            float sum = 0.f;
            #pragma unroll
            for (int nt = 0; nt < 8; nt++) {
                float p0 = exp2f(s[nt][2*r]   - mn);
                float p1 = exp2f(s[nt][2*r+1] - mn);
                s[nt][2*r] = p0; s[nt][2*r+1] = p1;
                sum += p0 + p1;
            }
            sum += __shfl_xor_sync(0xffffffffu, sum, 1);
            sum += __shfl_xor_sync(0xffffffffu, sum, 2);
            l_run[r] = l_run[r]*corr + sum;
            m_run[r] = mn;
            #pragma unroll
            for (int nt = 0; nt < 4; nt++) {
                o[nt][2*r]   *= corr;
                o[nt][2*r+1] *= corr;
            }
        }

        // P -> warp-private smem rows (raw fp32, HW truncates to tf32)
        #pragma unroll
        for (int nt = 0; nt < 8; nt++) {
            int c0 = nt*8 + (lane & 3)*2;
            *(float2*)&Ps[lr*PS_PITCH + c0]     = make_float2(s[nt][0], s[nt][1]);
            *(float2*)&Ps[(lr+8)*PS_PITCH + c0] = make_float2(s[nt][2], s[nt][3]);
        }
        __syncwarp();

        // O += P @ V
        #pragma unroll
        for (int kk = 0; kk < 8; kk++) {
            const int c = kk*8 + (lane & 3);
            unsigned af[4], bf[4][2];
            af[0] = __float_as_uint(Ps[lr*PS_PITCH + c]);
            af[1] = __float_as_uint(Ps[(lr+8)*PS_PITCH + c]);
            af[2] = __float_as_uint(Ps[lr*PS_PITCH + c + 4]);
            af[3] = __float_as_uint(Ps[(lr+8)*PS_PITCH + c + 4]);
            #pragma unroll
            for (int nt = 0; nt < 4; nt++) {
                int n = nt*8 + (lane >> 2);
                bf[nt][0] = __float_as_uint(fV[c*40 + n]);
                bf[nt][1] = __float_as_uint(fV[(c+4)*40 + n]);
            }
            #pragma unroll
            for (int nt = 0; nt < 4; nt++)
                mma_tf32(o[nt], af, bf[nt]);
        }
        __syncthreads();
    }

    const int b = bh / NHc, h = bh % NHc;
    const float inv0 = 1.0f / l_run[0];
    const float inv1 = 1.0f / l_run[1];
    #pragma unroll
    for (int nt = 0; nt < 4; nt++) {
        int d = nt*8 + (lane & 3)*2;
        float* y0 = g_y + (size_t)(b*Tc + gr0)*Dc + h*HDc + d;
        *(float2*)y0 = make_float2(__uint_as_float(f2tf(o[nt][0]*inv0)),
                                   __uint_as_float(f2tf(o[nt][1]*inv0)));
        float* y1 = g_y + (size_t)(b*Tc + gr1)*Dc + h*HDc + d;
        *(float2*)y1 = make_float2(__uint_as_float(f2tf(o[nt][2]*inv1)),
                                   __uint_as_float(f2tf(o[nt][3]*inv1)));
    }
}

extern "C" void kernel_launch(void* const* d_in, const int* in_sizes, int n_in,
                              void* d_out, int out_size) {
    const float* x    = (const float*)d_in[0];
    const float* Wq   = (const float*)d_in[1];
    const float* Wk   = (const float*)d_in[2];
    const float* Wv   = (const float*)d_in[3];
    const float* Wp   = (const float*)d_in[4];
    const float* gain = (const float*)d_in[5];
    const float* cosb = (const float*)d_in[6];
    const float* sinb = (const float*)d_in[7];

    const int gemm_smem = 6 * 4608 * 4;                                 // 110592 B
    const int attn_smem = (4608 + 128*PS_PITCH + 2*2304 + 2*2560) * 4;  // 92160 B
    cudaFuncSetAttribute(qkv_fused, cudaFuncAttributeMaxDynamicSharedMemorySize, gemm_smem);
    cudaFuncSetAttribute(proj_gemm, cudaFuncAttributeMaxDynamicSharedMemorySize, gemm_smem);
    cudaFuncSetAttribute(attn_mma,  cudaFuncAttributeMaxDynamicSharedMemorySize, attn_smem);

    const long nprep = (long)Mc*Dc/4 + 4L*Dc*Dc/4;
    prep_tf32<<<(int)((nprep + 255)/256), 256>>>(x, Wq, Wk, Wv, Wp);
    qkv_fused<<<dim3(Dc/128, Mc/128, 3), 256, gemm_smem>>>(gain, cosb, sinb);
    attn_mma<<<dim3(Tc/128, Bc*NHc), 256, attn_smem>>>();
    proj_gemm<<<dim3(Dc/128, Mc/128), 256, gemm_smem>>>((float*)d_out);
}

// round 7
// speedup vs baseline: 6.2668x; 1.6244x over previous
#include <cuda_runtime.h>
#include <cuda_fp16.h>

#define Bc  2
#define Tc  2048
#define Dc  1024
#define NHc 32
#define HDc 32
#define Mc  (Bc*Tc)   // 4096

// Scratch (allocation-free rule: __device__ globals). All fp16.
__device__ half g_xh[Mc*Dc];
__device__ half g_wqh[Dc*Dc];
__device__ half g_wkh[Dc*Dc];
__device__ half g_wvh[Dc*Dc];
__device__ half g_wph[Dc*Dc];
__device__ half g_q[Bc*NHc*Tc*HDc];   // [B,NH,T,HD] post rope*gain*scale*log2e
__device__ half g_k[Bc*NHc*Tc*HDc];   // [B,NH,T,HD] post rope
__device__ half g_vt[Bc*NHc*HDc*Tc];  // [B,NH,HD,T]  (transposed!)
__device__ half g_y[Mc*Dc];           // attn out

__device__ __forceinline__ void mma_f16(float* c, const unsigned* a, const unsigned* b) {
    asm volatile(
        "mma.sync.aligned.m16n8k16.row.col.f32.f16.f16.f32 "
        "{%0,%1,%2,%3}, {%4,%5,%6,%7}, {%8,%9}, {%0,%1,%2,%3};"
        : "+f"(c[0]), "+f"(c[1]), "+f"(c[2]), "+f"(c[3])
        : "r"(a[0]), "r"(a[1]), "r"(a[2]), "r"(a[3]), "r"(b[0]), "r"(b[1]));
}

__device__ __forceinline__ void cp16(unsigned s, const void* g) {
    asm volatile("cp.async.cg.shared.global [%0], [%1], 16;" :: "r"(s), "l"(g));
}
#define CP_COMMIT()  asm volatile("cp.async.commit_group;")
#define CP_WAIT1()   asm volatile("cp.async.wait_group 1;")
#define CP_WAIT0()   asm volatile("cp.async.wait_group 0;")

// ---------------------------------------------------------------------------
// Prepass: fp32 -> fp16 (RN) for x and the 4 weights.
// ---------------------------------------------------------------------------
__global__ void prep_half(const float* __restrict__ x,  const float* __restrict__ wq,
                          const float* __restrict__ wk, const float* __restrict__ wv,
                          const float* __restrict__ wp) {
    const long NX = (long)Mc*Dc/4;
    const long NW = (long)Dc*Dc/4;
    long i = (long)blockIdx.x*blockDim.x + threadIdx.x;
    if (i >= NX + 4*NW) return;
    const float4* s; half2* d; long o;
    if (i < NX) { s = (const float4*)x + i; d = (half2*)g_xh; o = i; }
    else {
        long j = i - NX; int w = (int)(j / NW); o = j % NW;
        const float* sw = (w == 0) ? wq : (w == 1) ? wk : (w == 2) ? wv : wp;
        half* dw = (w == 0) ? g_wqh : (w == 1) ? g_wkh : (w == 2) ? g_wvh : g_wph;
        s = (const float4*)sw + o; d = (half2*)dw;
    }
    float4 v = *s;
    d[2*o]   = __floats2half2_rn(v.x, v.y);
    d[2*o+1] = __floats2half2_rn(v.z, v.w);
}

// ---------------------------------------------------------------------------
// GEMM core constants: 128x128 tile, Kstep 32 (2x k16), pitch 20 half2/row.
// ---------------------------------------------------------------------------
#define PH  20
#define STW (128*PH)   // 2560 words per stage per matrix

// ---------------------------------------------------------------------------
// Fused QKV GEMM (fp16 MMA) + RMSNorm + RoPE (+gain*scale*log2e for q).
// ---------------------------------------------------------------------------
__global__ void __launch_bounds__(256, 2)
qkv_fused(const float* __restrict__ gain,
          const float* __restrict__ cosb,
          const float* __restrict__ sinb) {
    extern __shared__ unsigned smu[];
    unsigned* As = smu;             // [3][2560]
    unsigned* Bs = smu + 3*STW;
    const unsigned as_u = (unsigned)__cvta_generic_to_shared(As);
    const unsigned bs_u = (unsigned)__cvta_generic_to_shared(Bs);

    const int z = blockIdx.z;
    const half* W = (z == 0) ? g_wqh : (z == 1) ? g_wkh : g_wvh;
    const int m0 = blockIdx.y * 128, n0 = blockIdx.x * 128;
    const int tid = threadIdx.x, lane = tid & 31, wid = tid >> 5;
    const int wm = wid >> 2, wn = wid & 3;

    float acc[4][4][4] = {};

    auto load_stage = [&](int buf, int k0) {
        #pragma unroll
        for (int i = 0; i < 2; i++) {
            int idx = tid + i * 256;
            int row = idx >> 2, ci = idx & 3;
            cp16(as_u + (buf*STW + row*PH + ci*4)*4,
                 &g_xh[(size_t)(m0 + row)*Dc + k0 + ci*8]);
            cp16(bs_u + (buf*STW + row*PH + ci*4)*4,
                 &W[(size_t)(n0 + row)*Dc + k0 + ci*8]);
        }
        CP_COMMIT();
    };

    load_stage(0, 0);
    load_stage(1, 32);
    int buf = 0;
    for (int ks = 0; ks < 32; ks++) {
        if (ks == 31) { CP_WAIT0(); } else { CP_WAIT1(); }
        __syncthreads();
        if (ks + 2 < 32) {
            int nb = buf + 2; if (nb >= 3) nb -= 3;
            load_stage(nb, (ks + 2) * 32);
        }
        const unsigned* fA = As + buf*STW;
        const unsigned* fB = Bs + buf*STW;
        #pragma unroll
        for (int kk = 0; kk < 2; kk++) {
            const int c = kk*8 + (lane & 3);
            unsigned af[4][4], bf[4][2];
            #pragma unroll
            for (int mt = 0; mt < 4; mt++) {
                int r = wm*64 + mt*16 + (lane >> 2);
                af[mt][0] = fA[r*PH + c];     af[mt][1] = fA[(r+8)*PH + c];
                af[mt][2] = fA[r*PH + c + 4]; af[mt][3] = fA[(r+8)*PH + c + 4];
            }
            #pragma unroll
            for (int nt = 0; nt < 4; nt++) {
                int n = wn*32 + nt*8 + (lane >> 2);
                bf[nt][0] = fB[n*PH + c]; bf[nt][1] = fB[n*PH + c + 4];
            }
            #pragma unroll
            for (int mt = 0; mt < 4; mt++)
                #pragma unroll
                for (int nt = 0; nt < 4; nt++)
                    mma_f16(acc[mt][nt], af[mt], bf[nt]);
        }
        if (++buf >= 3) buf = 0;
    }

    const int h = (n0 >> 5) + wn;   // warp's 32-col slab == one head
    const int bh = 0;  (void)bh;
    if (z == 2) {
        // V: store TRANSPOSED [B,NH,HD,T]
        #pragma unroll
        for (int mt = 0; mt < 4; mt++) {
            int r0 = m0 + wm*64 + mt*16 + (lane >> 2);
            int b = r0 >> 11, t = r0 & 2047;
            #pragma unroll
            for (int nt = 0; nt < 4; nt++) {
                int d = nt*8 + (lane & 3)*2;
                size_t base = ((size_t)((b*NHc + h)*HDc + d))*Tc;
                g_vt[base + t]          = __float2half_rn(acc[mt][nt][0]);
                g_vt[base + Tc + t]     = __float2half_rn(acc[mt][nt][1]);
                g_vt[base + t + 8]      = __float2half_rn(acc[mt][nt][2]);
                g_vt[base + Tc + t + 8] = __float2half_rn(acc[mt][nt][3]);
            }
        }
        return;
    }

    // q/k: RMSNorm (quad reduce) + RoPE (partner = nt^2).
    half2* out2 = (half2*)((z == 0) ? g_q : g_k);
    const float gn = (z == 0)
        ? gain[h] * 0.17677669529663687f * 1.4426950408889634f : 1.0f;
    #pragma unroll
    for (int mt = 0; mt < 4; mt++) {
        int r0 = m0 + wm*64 + mt*16 + (lane >> 2);
        int b = r0 >> 11, t0 = r0 & 2047;

        float ss0 = 0.f, ss1 = 0.f;
        #pragma unroll
        for (int nt = 0; nt < 4; nt++) {
            ss0 += acc[mt][nt][0]*acc[mt][nt][0] + acc[mt][nt][1]*acc[mt][nt][1];
            ss1 += acc[mt][nt][2]*acc[mt][nt][2] + acc[mt][nt][3]*acc[mt][nt][3];
        }
        ss0 += __shfl_xor_sync(0xffffffffu, ss0, 1);
        ss0 += __shfl_xor_sync(0xffffffffu, ss0, 2);
        ss1 += __shfl_xor_sync(0xffffffffu, ss1, 1);
        ss1 += __shfl_xor_sync(0xffffffffu, ss1, 2);
        float sc0 = rsqrtf(ss0 * (1.0f/HDc) + 1e-6f) * gn;
        float sc1 = rsqrtf(ss1 * (1.0f/HDc) + 1e-6f) * gn;

        float nv[4][4];
        #pragma unroll
        for (int nt = 0; nt < 4; nt++) {
            nv[nt][0] = acc[mt][nt][0]*sc0; nv[nt][1] = acc[mt][nt][1]*sc0;
            nv[nt][2] = acc[mt][nt][2]*sc1; nv[nt][3] = acc[mt][nt][3]*sc1;
        }
        #pragma unroll
        for (int nt = 0; nt < 4; nt++) {
            int d  = nt*8 + (lane & 3)*2;
            int dh = d & 15;
            float c00 = cosb[t0*16 + dh],     s00 = sinb[t0*16 + dh];
            float c01 = cosb[t0*16 + dh + 1], s01 = sinb[t0*16 + dh + 1];
            float c10 = cosb[(t0+8)*16 + dh],     s10 = sinb[(t0+8)*16 + dh];
            float c11 = cosb[(t0+8)*16 + dh + 1], s11 = sinb[(t0+8)*16 + dh + 1];
            float o0, o1, o2, o3;
            if (nt < 2) {
                o0 = nv[nt][0]*c00 - nv[nt^2][0]*s00;
                o1 = nv[nt][1]*c01 - nv[nt^2][1]*s01;
                o2 = nv[nt][2]*c10 - nv[nt^2][2]*s10;
                o3 = nv[nt][3]*c11 - nv[nt^2][3]*s11;
            } else {
                o0 = nv[nt][0]*c00 + nv[nt^2][0]*s00;
                o1 = nv[nt][1]*c01 + nv[nt^2][1]*s01;
                o2 = nv[nt][2]*c10 + nv[nt^2][2]*s10;
                o3 = nv[nt][3]*c11 + nv[nt^2][3]*s11;
            }
            size_t rowi = (size_t)((b*NHc + h)*Tc);
            out2[(rowi + t0)*16 + nt*4 + (lane & 3)]     = __floats2half2_rn(o0, o1);
            out2[(rowi + t0 + 8)*16 + nt*4 + (lane & 3)] = __floats2half2_rn(o2, o3);
        }
    }
}

// ---------------------------------------------------------------------------
// Output projection: d_out(fp32) = g_y @ Wproj^T, fp16 MMA.
// ---------------------------------------------------------------------------
__global__ void __launch_bounds__(256, 2)
proj_gemm(float* __restrict__ out) {
    extern __shared__ unsigned smu[];
    unsigned* As = smu;
    unsigned* Bs = smu + 3*STW;
    const unsigned as_u = (unsigned)__cvta_generic_to_shared(As);
    const unsigned bs_u = (unsigned)__cvta_generic_to_shared(Bs);

    const int m0 = blockIdx.y * 128, n0 = blockIdx.x * 128;
    const int tid = threadIdx.x, lane = tid & 31, wid = tid >> 5;
    const int wm = wid >> 2, wn = wid & 3;

    float acc[4][4][4] = {};

    auto load_stage = [&](int buf, int k0) {
        #pragma unroll
        for (int i = 0; i < 2; i++) {
            int idx = tid + i * 256;
            int row = idx >> 2, ci = idx & 3;
            cp16(as_u + (buf*STW + row*PH + ci*4)*4,
                 &g_y[(size_t)(m0 + row)*Dc + k0 + ci*8]);
            cp16(bs_u + (buf*STW + row*PH + ci*4)*4,
                 &g_wph[(size_t)(n0 + row)*Dc + k0 + ci*8]);
        }
        CP_COMMIT();
    };

    load_stage(0, 0);
    load_stage(1, 32);
    int buf = 0;
    for (int ks = 0; ks < 32; ks++) {
        if (ks == 31) { CP_WAIT0(); } else { CP_WAIT1(); }
        __syncthreads();
        if (ks + 2 < 32) {
            int nb = buf + 2; if (nb >= 3) nb -= 3;
            load_stage(nb, (ks + 2) * 32);
        }
        const unsigned* fA = As + buf*STW;
        const unsigned* fB = Bs + buf*STW;
        #pragma unroll
        for (int kk = 0; kk < 2; kk++) {
            const int c = kk*8 + (lane & 3);
            unsigned af[4][4], bf[4][2];
            #pragma unroll
            for (int mt = 0; mt < 4; mt++) {
                int r = wm*64 + mt*16 + (lane >> 2);
                af[mt][0] = fA[r*PH + c];     af[mt][1] = fA[(r+8)*PH + c];
                af[mt][2] = fA[r*PH + c + 4]; af[mt][3] = fA[(r+8)*PH + c + 4];
            }
            #pragma unroll
            for (int nt = 0; nt < 4; nt++) {
                int n = wn*32 + nt*8 + (lane >> 2);
                bf[nt][0] = fB[n*PH + c]; bf[nt][1] = fB[n*PH + c + 4];
            }
            #pragma unroll
            for (int mt = 0; mt < 4; mt++)
                #pragma unroll
                for (int nt = 0; nt < 4; nt++)
                    mma_f16(acc[mt][nt], af[mt], bf[nt]);
        }
        if (++buf >= 3) buf = 0;
    }

    #pragma unroll
    for (int mt = 0; mt < 4; mt++) {
        int r0 = m0 + wm*64 + mt*16 + (lane >> 2);
        #pragma unroll
        for (int nt = 0; nt < 4; nt++) {
            int c0 = n0 + wn*32 + nt*8 + (lane & 3)*2;
            *(float2*)&out[(size_t)r0*Dc + c0] =
                make_float2(acc[mt][nt][0], acc[mt][nt][1]);
            *(float2*)&out[(size_t)(r0+8)*Dc + c0] =
                make_float2(acc[mt][nt][2], acc[mt][nt][3]);
        }
    }
}

// ---------------------------------------------------------------------------
// Flash attention, fp16 MMA, exp2 softmax. CTA: 128 q, 8 warps, 64-key blocks,
// 2-stage cp.async K/Vt. Q fragments in registers. Longest blocks first.
// K pitch 20 half2, Vt/P pitch 36 half2.
// ---------------------------------------------------------------------------
__global__ void __launch_bounds__(256, 2)
attn_mma() {
    extern __shared__ unsigned smu[];
    unsigned* Ps = smu;                   // 128 x 36  (4608 words)
    unsigned* Ks = smu + 4608;            // 2 x 64 x 20 (2560)
    unsigned* Vs = smu + 4608 + 2560;     // 2 x 32 x 36 (2304)
    const unsigned ks_u = (unsigned)__cvta_generic_to_shared(Ks);
    const unsigned vs_u = (unsigned)__cvta_generic_to_shared(Vs);

    const int bh = blockIdx.y;
    const int q0 = ((int)gridDim.x - 1 - (int)blockIdx.x) * 128;  // longest first
    const half* kp  = g_k  + (size_t)bh * Tc * HDc;
    const half* vtp = g_vt + (size_t)bh * HDc * Tc;
    const int tid = threadIdx.x, lane = tid & 31, wid = tid >> 5;

    auto load_kv = [&](int buf, int k0) {
        cp16(ks_u + (buf*1280 + (tid>>2)*20 + (tid&3)*4)*4,
             &kp[(size_t)(k0 + (tid>>2))*HDc + (tid&3)*8]);
        cp16(vs_u + (buf*1152 + (tid>>3)*36 + (tid&7)*4)*4,
             &vtp[(size_t)(tid>>3)*Tc + k0 + (tid&7)*8]);
        CP_COMMIT();
    };

    load_kv(0, 0);

    const int lr = wid*16 + (lane >> 2);
    const int gr0 = q0 + lr, gr1 = gr0 + 8;

    // Q fragments in registers (reused every key block)
    unsigned qf[2][4];
    {
        const unsigned* qu = (const unsigned*)g_q + (size_t)bh * Tc * 16;
        #pragma unroll
        for (int kk = 0; kk < 2; kk++) {
            int cq = kk*8 + (lane & 3);
            qf[kk][0] = qu[(size_t)gr0*16 + cq];
            qf[kk][1] = qu[(size_t)gr1*16 + cq];
            qf[kk][2] = qu[(size_t)gr0*16 + cq + 4];
            qf[kk][3] = qu[(size_t)gr1*16 + cq + 4];
        }
    }

    float m_run[2] = {-1e30f, -1e30f};
    float l_run[2] = {0.f, 0.f};
    float o[4][4] = {};

    const int nkb = (q0 + 128) / 64;
    for (int kb = 0; kb < nkb; kb++) {
        const int k0 = kb * 64;
        const int buf = kb & 1;
        if (kb + 1 < nkb) { load_kv(buf ^ 1, (kb + 1) * 64); CP_WAIT1(); }
        else              { CP_WAIT0(); }
        __syncthreads();

        const unsigned* fK = Ks + buf*1280;
        const unsigned* fV = Vs + buf*1152;

        // S = Q @ K^T : 16 q-rows x 64 keys per warp
        float s[8][4] = {};
        #pragma unroll
        for (int kk = 0; kk < 2; kk++) {
            const int c = kk*8 + (lane & 3);
            #pragma unroll
            for (int nt = 0; nt < 8; nt++) {
                int n = nt*8 + (lane >> 2);
                unsigned bf[2] = { fK[n*20 + c], fK[n*20 + c + 4] };
                mma_f16(s[nt], qf[kk], bf);
            }
        }

        if (k0 + 63 > q0 + wid*16) {   // causal mask
            #pragma unroll
            for (int nt = 0; nt < 8; nt++) {
                int c0 = k0 + nt*8 + (lane & 3)*2;
                if (c0     > gr0) s[nt][0] = -1e30f;
                if (c0 + 1 > gr0) s[nt][1] = -1e30f;
                if (c0     > gr1) s[nt][2] = -1e30f;
                if (c0 + 1 > gr1) s[nt][3] = -1e30f;
            }
        }

        // online softmax, base-2
        #pragma unroll
        for (int r = 0; r < 2; r++) {
            float mx = -1e30f;
            #pragma unroll
            for (int nt = 0; nt < 8; nt++)
                mx = fmaxf(mx, fmaxf(s[nt][2*r], s[nt][2*r+1]));
            mx = fmaxf(mx, __shfl_xor_sync(0xffffffffu, mx, 1));
            mx = fmaxf(mx, __shfl_xor_sync(0xffffffffu, mx, 2));
            float mn = fmaxf(m_run[r], mx);
            float corr = exp2f(m_run[r] - mn);
            float sum = 0.f;
            #pragma unroll
            for (int nt = 0; nt < 8; nt++) {
                float p0 = exp2f(s[nt][2*r]   - mn);
                float p1 = exp2f(s[nt][2*r+1] - mn);
                s[nt][2*r] = p0; s[nt][2*r+1] = p1;
                sum += p0 + p1;
            }
            sum += __shfl_xor_sync(0xffffffffu, sum, 1);
            sum += __shfl_xor_sync(0xffffffffu, sum, 2);
            l_run[r] = l_run[r]*corr + sum;
            m_run[r] = mn;
            #pragma unroll
            for (int nt = 0; nt < 4; nt++) {
                o[nt][2*r]   *= corr;
                o[nt][2*r+1] *= corr;
            }
        }

        // P -> smem as half2 (one STS.32 per pair)
        #pragma unroll
        for (int nt = 0; nt < 8; nt++) {
            int pc = nt*4 + (lane & 3);
            *(half2*)&Ps[lr*36 + pc]     = __floats2half2_rn(s[nt][0], s[nt][1]);
            *(half2*)&Ps[(lr+8)*36 + pc] = __floats2half2_rn(s[nt][2], s[nt][3]);
        }
        __syncwarp();

        // O += P @ V  (k = 64 keys via 4x k16, n = 32 dims)
        #pragma unroll
        for (int kk = 0; kk < 4; kk++) {
            const int c = kk*8 + (lane & 3);
            unsigned af[4];
            af[0] = Ps[lr*36 + c];     af[1] = Ps[(lr+8)*36 + c];
            af[2] = Ps[lr*36 + c + 4]; af[3] = Ps[(lr+8)*36 + c + 4];
            #pragma unroll
            for (int nt = 0; nt < 4; nt++) {
                int n = nt*8 + (lane >> 2);
                unsigned bf[2] = { fV[n*36 + c], fV[n*36 + c + 4] };
                mma_f16(o[nt], af, bf);
            }
        }
        __syncthreads();
    }

    const int b = bh / NHc, h = bh % NHc;
    const float inv0 = 1.0f / l_run[0];
    const float inv1 = 1.0f / l_run[1];
    half2* y2 = (half2*)g_y;
    #pragma unroll
    for (int nt = 0; nt < 4; nt++) {
        int pc = nt*4 + (lane & 3);           // d/2
        y2[((size_t)(b*Tc + gr0))*512 + h*16 + pc] =
            __floats2half2_rn(o[nt][0]*inv0, o[nt][1]*inv0);
        y2[((size_t)(b*Tc + gr1))*512 + h*16 + pc] =
            __floats2half2_rn(o[nt][2]*inv1, o[nt][3]*inv1);
    }
}

extern "C" void kernel_launch(void* const* d_in, const int* in_sizes, int n_in,
                              void* d_out, int out_size) {
    const float* x    = (const float*)d_in[0];
    const float* Wq   = (const float*)d_in[1];
    const float* Wk   = (const float*)d_in[2];
    const float* Wv   = (const float*)d_in[3];
    const float* Wp   = (const float*)d_in[4];
    const float* gain = (const float*)d_in[5];
    const float* cosb = (const float*)d_in[6];
    const float* sinb = (const float*)d_in[7];

    const int gemm_smem = 6 * STW * 4;                  // 61440 B
    const int attn_smem = (4608 + 2560 + 2304) * 4;     // 37888 B
    cudaFuncSetAttribute(qkv_fused, cudaFuncAttributeMaxDynamicSharedMemorySize, gemm_smem);
    cudaFuncSetAttribute(proj_gemm, cudaFuncAttributeMaxDynamicSharedMemorySize, gemm_smem);
    cudaFuncSetAttribute(attn_mma,  cudaFuncAttributeMaxDynamicSharedMemorySize, attn_smem);

    const long nprep = (long)Mc*Dc/4 + 4L*Dc*Dc/4;
    prep_half<<<(int)((nprep + 255)/256), 256>>>(x, Wq, Wk, Wv, Wp);
    qkv_fused<<<dim3(Dc/128, Mc/128, 3), 256, gemm_smem>>>(gain, cosb, sinb);
    attn_mma<<<dim3(Tc/128, Bc*NHc), 256, attn_smem>>>();
    proj_gemm<<<dim3(Dc/128, Mc/128), 256, gemm_smem>>>((float*)d_out);
}

// round 8
// speedup vs baseline: 6.8357x; 1.0908x over previous
#include <cuda_runtime.h>
#include <cuda_fp16.h>

#define Bc  2
#define Tc  2048
#define Dc  1024
#define NHc 32
#define HDc 32
#define Mc  (Bc*Tc)   // 4096

// Scratch (allocation-free rule: __device__ globals). All fp16.
__device__ half g_xh[Mc*Dc];
__device__ half g_wqh[Dc*Dc];
__device__ half g_wkh[Dc*Dc];
__device__ half g_wvh[Dc*Dc];
__device__ half g_wph[Dc*Dc];
__device__ half g_q[Bc*NHc*Tc*HDc];   // [B,NH,T,HD] post rope*gain*scale*log2e
__device__ half g_k[Bc*NHc*Tc*HDc];   // [B,NH,T,HD] post rope
__device__ half g_vt[Bc*NHc*HDc*Tc];  // [B,NH,HD,T]  (transposed!)
__device__ half g_y[Mc*Dc];           // attn out

__device__ __forceinline__ void mma_f16(float* c, const unsigned* a, const unsigned* b) {
    asm volatile(
        "mma.sync.aligned.m16n8k16.row.col.f32.f16.f16.f32 "
        "{%0,%1,%2,%3}, {%4,%5,%6,%7}, {%8,%9}, {%0,%1,%2,%3};"
        : "+f"(c[0]), "+f"(c[1]), "+f"(c[2]), "+f"(c[3])
        : "r"(a[0]), "r"(a[1]), "r"(a[2]), "r"(a[3]), "r"(b[0]), "r"(b[1]));
}

__device__ __forceinline__ void ldsm4(unsigned& r0, unsigned& r1, unsigned& r2,
                                      unsigned& r3, unsigned addr) {
    asm volatile("ldmatrix.sync.aligned.m8n8.x4.shared.b16 {%0,%1,%2,%3}, [%4];"
                 : "=r"(r0), "=r"(r1), "=r"(r2), "=r"(r3) : "r"(addr));
}

__device__ __forceinline__ void cp16(unsigned s, const void* g) {
    asm volatile("cp.async.cg.shared.global [%0], [%1], 16;" :: "r"(s), "l"(g));
}
#define CP_COMMIT()  asm volatile("cp.async.commit_group;")
#define CP_WAIT1()   asm volatile("cp.async.wait_group 1;")
#define CP_WAIT0()   asm volatile("cp.async.wait_group 0;")

// ---------------------------------------------------------------------------
// Prepass: fp32 -> fp16 (RN) for x and the 4 weights.
// ---------------------------------------------------------------------------
__global__ void prep_half(const float* __restrict__ x,  const float* __restrict__ wq,
                          const float* __restrict__ wk, const float* __restrict__ wv,
                          const float* __restrict__ wp) {
    const long NX = (long)Mc*Dc/4;
    const long NW = (long)Dc*Dc/4;
    long i = (long)blockIdx.x*blockDim.x + threadIdx.x;
    if (i >= NX + 4*NW) return;
    const float4* s; half2* d; long o;
    if (i < NX) { s = (const float4*)x + i; d = (half2*)g_xh; o = i; }
    else {
        long j = i - NX; int w = (int)(j / NW); o = j % NW;
        const float* sw = (w == 0) ? wq : (w == 1) ? wk : (w == 2) ? wv : wp;
        half* dw = (w == 0) ? g_wqh : (w == 1) ? g_wkh : (w == 2) ? g_wvh : g_wph;
        s = (const float4*)sw + o; d = (half2*)dw;
    }
    float4 v = *s;
    d[2*o]   = __floats2half2_rn(v.x, v.y);
    d[2*o+1] = __floats2half2_rn(v.z, v.w);
}

#define PH  20
#define STW (128*PH)   // 2560 words per stage per matrix

// ---------------------------------------------------------------------------
// Fused QKV GEMM (fp16 MMA + ldmatrix) + RMSNorm + RoPE epilogue.
// ---------------------------------------------------------------------------
__global__ void __launch_bounds__(256, 2)
qkv_fused(const float* __restrict__ gain,
          const float* __restrict__ cosb,
          const float* __restrict__ sinb) {
    extern __shared__ unsigned smu[];
    unsigned* As = smu;             // [3][2560]
    unsigned* Bs = smu + 3*STW;
    const unsigned as_u = (unsigned)__cvta_generic_to_shared(As);
    const unsigned bs_u = (unsigned)__cvta_generic_to_shared(Bs);

    const int z = blockIdx.z;
    const half* W = (z == 0) ? g_wqh : (z == 1) ? g_wkh : g_wvh;
    const int m0 = blockIdx.y * 128, n0 = blockIdx.x * 128;
    const int tid = threadIdx.x, lane = tid & 31, wid = tid >> 5;
    const int wm = wid >> 2, wn = wid & 3;

    float acc[4][4][4] = {};

    auto load_stage = [&](int buf, int k0) {
        #pragma unroll
        for (int i = 0; i < 2; i++) {
            int idx = tid + i * 256;
            int row = idx >> 2, ci = idx & 3;
            cp16(as_u + (buf*STW + row*PH + ci*4)*4,
                 &g_xh[(size_t)(m0 + row)*Dc + k0 + ci*8]);
            cp16(bs_u + (buf*STW + row*PH + ci*4)*4,
                 &W[(size_t)(n0 + row)*Dc + k0 + ci*8]);
        }
        CP_COMMIT();
    };

    // LDSM lane-address components
    const int a_r  = lane & 15;            // row within 16-row A tile
    const int a_ch = (lane >> 4) << 2;     // +4 words for k8-15 half
    const int b_r  = lane & 7;
    const int b_nt = (lane >> 4) & 1;      // nt or nt+1
    const int b_ch = ((lane >> 3) & 1) << 2;

    load_stage(0, 0);
    load_stage(1, 32);
    int buf = 0;
    for (int ks = 0; ks < 32; ks++) {
        if (ks == 31) { CP_WAIT0(); } else { CP_WAIT1(); }
        __syncthreads();
        if (ks + 2 < 32) {
            int nb = buf + 2; if (nb >= 3) nb -= 3;
            load_stage(nb, (ks + 2) * 32);
        }
        #pragma unroll
        for (int kk = 0; kk < 2; kk++) {
            unsigned af[4][4], bf[2][4];
            #pragma unroll
            for (int mt = 0; mt < 4; mt++) {
                int r = wm*64 + mt*16 + a_r;
                ldsm4(af[mt][0], af[mt][1], af[mt][2], af[mt][3],
                      as_u + (buf*STW + r*PH + kk*8 + a_ch)*4);
            }
            #pragma unroll
            for (int np = 0; np < 2; np++) {
                int n = wn*32 + np*16 + b_nt*8 + b_r;
                ldsm4(bf[np][0], bf[np][1], bf[np][2], bf[np][3],
                      bs_u + (buf*STW + n*PH + kk*8 + b_ch)*4);
            }
            #pragma unroll
            for (int mt = 0; mt < 4; mt++)
                #pragma unroll
                for (int np = 0; np < 2; np++) {
                    mma_f16(acc[mt][np*2],   af[mt], &bf[np][0]);
                    mma_f16(acc[mt][np*2+1], af[mt], &bf[np][2]);
                }
        }
        if (++buf >= 3) buf = 0;
    }

    const int h = (n0 >> 5) + wn;   // warp's 32-col slab == one head
    if (z == 2) {
        // V: store TRANSPOSED [B,NH,HD,T]
        #pragma unroll
        for (int mt = 0; mt < 4; mt++) {
            int r0 = m0 + wm*64 + mt*16 + (lane >> 2);
            int b = r0 >> 11, t = r0 & 2047;
            #pragma unroll
            for (int nt = 0; nt < 4; nt++) {
                int d = nt*8 + (lane & 3)*2;
                size_t base = ((size_t)((b*NHc + h)*HDc + d))*Tc;
                g_vt[base + t]          = __float2half_rn(acc[mt][nt][0]);
                g_vt[base + Tc + t]     = __float2half_rn(acc[mt][nt][1]);
                g_vt[base + t + 8]      = __float2half_rn(acc[mt][nt][2]);
                g_vt[base + Tc + t + 8] = __float2half_rn(acc[mt][nt][3]);
            }
        }
        return;
    }

    // q/k: RMSNorm (quad reduce) + RoPE (partner = nt^2).
    half2* out2 = (half2*)((z == 0) ? g_q : g_k);
    const float gn = (z == 0)
        ? gain[h] * 0.17677669529663687f * 1.4426950408889634f : 1.0f;
    #pragma unroll
    for (int mt = 0; mt < 4; mt++) {
        int r0 = m0 + wm*64 + mt*16 + (lane >> 2);
        int b = r0 >> 11, t0 = r0 & 2047;

        float ss0 = 0.f, ss1 = 0.f;
        #pragma unroll
        for (int nt = 0; nt < 4; nt++) {
            ss0 += acc[mt][nt][0]*acc[mt][nt][0] + acc[mt][nt][1]*acc[mt][nt][1];
            ss1 += acc[mt][nt][2]*acc[mt][nt][2] + acc[mt][nt][3]*acc[mt][nt][3];
        }
        ss0 += __shfl_xor_sync(0xffffffffu, ss0, 1);
        ss0 += __shfl_xor_sync(0xffffffffu, ss0, 2);
        ss1 += __shfl_xor_sync(0xffffffffu, ss1, 1);
        ss1 += __shfl_xor_sync(0xffffffffu, ss1, 2);
        float sc0 = rsqrtf(ss0 * (1.0f/HDc) + 1e-6f) * gn;
        float sc1 = rsqrtf(ss1 * (1.0f/HDc) + 1e-6f) * gn;

        float nv[4][4];
        #pragma unroll
        for (int nt = 0; nt < 4; nt++) {
            nv[nt][0] = acc[mt][nt][0]*sc0; nv[nt][1] = acc[mt][nt][1]*sc0;
            nv[nt][2] = acc[mt][nt][2]*sc1; nv[nt][3] = acc[mt][nt][3]*sc1;
        }
        #pragma unroll
        for (int nt = 0; nt < 4; nt++) {
            int d  = nt*8 + (lane & 3)*2;
            int dh = d & 15;
            float c00 = cosb[t0*16 + dh],     s00 = sinb[t0*16 + dh];
            float c01 = cosb[t0*16 + dh + 1], s01 = sinb[t0*16 + dh + 1];
            float c10 = cosb[(t0+8)*16 + dh],     s10 = sinb[(t0+8)*16 + dh];
            float c11 = cosb[(t0+8)*16 + dh + 1], s11 = sinb[(t0+8)*16 + dh + 1];
            float o0, o1, o2, o3;
            if (nt < 2) {
                o0 = nv[nt][0]*c00 - nv[nt^2][0]*s00;
                o1 = nv[nt][1]*c01 - nv[nt^2][1]*s01;
                o2 = nv[nt][2]*c10 - nv[nt^2][2]*s10;
                o3 = nv[nt][3]*c11 - nv[nt^2][3]*s11;
            } else {
                o0 = nv[nt][0]*c00 + nv[nt^2][0]*s00;
                o1 = nv[nt][1]*c01 + nv[nt^2][1]*s01;
                o2 = nv[nt][2]*c10 + nv[nt^2][2]*s10;
                o3 = nv[nt][3]*c11 + nv[nt^2][3]*s11;
            }
            size_t rowi = (size_t)((b*NHc + h)*Tc);
            out2[(rowi + t0)*16 + nt*4 + (lane & 3)]     = __floats2half2_rn(o0, o1);
            out2[(rowi + t0 + 8)*16 + nt*4 + (lane & 3)] = __floats2half2_rn(o2, o3);
        }
    }
}

// ---------------------------------------------------------------------------
// Output projection: d_out(fp32) = g_y @ Wproj^T, fp16 MMA + ldmatrix.
// ---------------------------------------------------------------------------
__global__ void __launch_bounds__(256, 2)
proj_gemm(float* __restrict__ out) {
    extern __shared__ unsigned smu[];
    unsigned* As = smu;
    unsigned* Bs = smu + 3*STW;
    const unsigned as_u = (unsigned)__cvta_generic_to_shared(As);
    const unsigned bs_u = (unsigned)__cvta_generic_to_shared(Bs);

    const int m0 = blockIdx.y * 128, n0 = blockIdx.x * 128;
    const int tid = threadIdx.x, lane = tid & 31, wid = tid >> 5;
    const int wm = wid >> 2, wn = wid & 3;

    float acc[4][4][4] = {};

    auto load_stage = [&](int buf, int k0) {
        #pragma unroll
        for (int i = 0; i < 2; i++) {
            int idx = tid + i * 256;
            int row = idx >> 2, ci = idx & 3;
            cp16(as_u + (buf*STW + row*PH + ci*4)*4,
                 &g_y[(size_t)(m0 + row)*Dc + k0 + ci*8]);
            cp16(bs_u + (buf*STW + row*PH + ci*4)*4,
                 &g_wph[(size_t)(n0 + row)*Dc + k0 + ci*8]);
        }
        CP_COMMIT();
    };

    const int a_r  = lane & 15;
    const int a_ch = (lane >> 4) << 2;
    const int b_r  = lane & 7;
    const int b_nt = (lane >> 4) & 1;
    const int b_ch = ((lane >> 3) & 1) << 2;

    load_stage(0, 0);
    load_stage(1, 32);
    int buf = 0;
    for (int ks = 0; ks < 32; ks++) {
        if (ks == 31) { CP_WAIT0(); } else { CP_WAIT1(); }
        __syncthreads();
        if (ks + 2 < 32) {
            int nb = buf + 2; if (nb >= 3) nb -= 3;
            load_stage(nb, (ks + 2) * 32);
        }
        #pragma unroll
        for (int kk = 0; kk < 2; kk++) {
            unsigned af[4][4], bf[2][4];
            #pragma unroll
            for (int mt = 0; mt < 4; mt++) {
                int r = wm*64 + mt*16 + a_r;
                ldsm4(af[mt][0], af[mt][1], af[mt][2], af[mt][3],
                      as_u + (buf*STW + r*PH + kk*8 + a_ch)*4);
            }
            #pragma unroll
            for (int np = 0; np < 2; np++) {
                int n = wn*32 + np*16 + b_nt*8 + b_r;
                ldsm4(bf[np][0], bf[np][1], bf[np][2], bf[np][3],
                      bs_u + (buf*STW + n*PH + kk*8 + b_ch)*4);
            }
            #pragma unroll
            for (int mt = 0; mt < 4; mt++)
                #pragma unroll
                for (int np = 0; np < 2; np++) {
                    mma_f16(acc[mt][np*2],   af[mt], &bf[np][0]);
                    mma_f16(acc[mt][np*2+1], af[mt], &bf[np][2]);
                }
        }
        if (++buf >= 3) buf = 0;
    }

    #pragma unroll
    for (int mt = 0; mt < 4; mt++) {
        int r0 = m0 + wm*64 + mt*16 + (lane >> 2);
        #pragma unroll
        for (int nt = 0; nt < 4; nt++) {
            int c0 = n0 + wn*32 + nt*8 + (lane & 3)*2;
            *(float2*)&out[(size_t)r0*Dc + c0] =
                make_float2(acc[mt][nt][0], acc[mt][nt][1]);
            *(float2*)&out[(size_t)(r0+8)*Dc + c0] =
                make_float2(acc[mt][nt][2], acc[mt][nt][3]);
        }
    }
}

// ---------------------------------------------------------------------------
// Flash attention, fp16 MMA + ldmatrix, exp2 softmax. 128 q/CTA, 8 warps,
// 64-key blocks, 2-stage cp.async K/Vt, Q fragments in registers.
// ---------------------------------------------------------------------------
__global__ void __launch_bounds__(256, 2)
attn_mma() {
    extern __shared__ unsigned smu[];
    unsigned* Ps = smu;                   // 128 x 36  (4608 words)
    unsigned* Ks = smu + 4608;            // 2 x 64 x 20 (2560)
    unsigned* Vs = smu + 4608 + 2560;     // 2 x 32 x 36 (2304)
    const unsigned ps_u = (unsigned)__cvta_generic_to_shared(Ps);
    const unsigned ks_u = (unsigned)__cvta_generic_to_shared(Ks);
    const unsigned vs_u = (unsigned)__cvta_generic_to_shared(Vs);

    const int bh = blockIdx.y;
    const int q0 = ((int)gridDim.x - 1 - (int)blockIdx.x) * 128;  // longest first
    const half* kp  = g_k  + (size_t)bh * Tc * HDc;
    const half* vtp = g_vt + (size_t)bh * HDc * Tc;
    const int tid = threadIdx.x, lane = tid & 31, wid = tid >> 5;

    auto load_kv = [&](int buf, int k0) {
        cp16(ks_u + (buf*1280 + (tid>>2)*20 + (tid&3)*4)*4,
             &kp[(size_t)(k0 + (tid>>2))*HDc + (tid&3)*8]);
        cp16(vs_u + (buf*1152 + (tid>>3)*36 + (tid&7)*4)*4,
             &vtp[(size_t)(tid>>3)*Tc + k0 + (tid&7)*8]);
        CP_COMMIT();
    };

    load_kv(0, 0);

    const int lr = wid*16 + (lane >> 2);
    const int gr0 = q0 + lr, gr1 = gr0 + 8;

    const int a_r  = lane & 15;
    const int a_ch = (lane >> 4) << 2;
    const int b_r  = lane & 7;
    const int b_nt = (lane >> 4) & 1;
    const int b_ch = ((lane >> 3) & 1) << 2;

    // Q fragments in registers
    unsigned qf[2][4];
    {
        const unsigned* qu = (const unsigned*)g_q + (size_t)bh * Tc * 16;
        #pragma unroll
        for (int kk = 0; kk < 2; kk++) {
            int cq = kk*8 + (lane & 3);
            qf[kk][0] = qu[(size_t)gr0*16 + cq];
            qf[kk][1] = qu[(size_t)gr1*16 + cq];
            qf[kk][2] = qu[(size_t)gr0*16 + cq + 4];
            qf[kk][3] = qu[(size_t)gr1*16 + cq + 4];
        }
    }

    float m_run[2] = {-1e30f, -1e30f};
    float l_run[2] = {0.f, 0.f};
    float o[4][4] = {};

    const int nkb = (q0 + 128) / 64;
    for (int kb = 0; kb < nkb; kb++) {
        const int k0 = kb * 64;
        const int buf = kb & 1;
        if (kb + 1 < nkb) { load_kv(buf ^ 1, (kb + 1) * 64); CP_WAIT1(); }
        else              { CP_WAIT0(); }
        __syncthreads();

        // S = Q @ K^T : 16 q-rows x 64 keys per warp
        float s[8][4] = {};
        #pragma unroll
        for (int kk = 0; kk < 2; kk++) {
            #pragma unroll
            for (int np = 0; np < 4; np++) {
                unsigned bf[4];
                int n = np*16 + b_nt*8 + b_r;
                ldsm4(bf[0], bf[1], bf[2], bf[3],
                      ks_u + (buf*1280 + n*20 + kk*8 + b_ch)*4);
                mma_f16(s[np*2],   qf[kk], &bf[0]);
                mma_f16(s[np*2+1], qf[kk], &bf[2]);
            }
        }

        if (k0 + 63 > q0 + wid*16) {   // causal mask
            #pragma unroll
            for (int nt = 0; nt < 8; nt++) {
                int c0 = k0 + nt*8 + (lane & 3)*2;
                if (c0     > gr0) s[nt][0] = -1e30f;
                if (c0 + 1 > gr0) s[nt][1] = -1e30f;
                if (c0     > gr1) s[nt][2] = -1e30f;
                if (c0 + 1 > gr1) s[nt][3] = -1e30f;
            }
        }

        // online softmax, base-2
        #pragma unroll
        for (int r = 0; r < 2; r++) {
            float mx = -1e30f;
            #pragma unroll
            for (int nt = 0; nt < 8; nt++)
                mx = fmaxf(mx, fmaxf(s[nt][2*r], s[nt][2*r+1]));
            mx = fmaxf(mx, __shfl_xor_sync(0xffffffffu, mx, 1));
            mx = fmaxf(mx, __shfl_xor_sync(0xffffffffu, mx, 2));
            float mn = fmaxf(m_run[r], mx);
            float corr = exp2f(m_run[r] - mn);
            float sum = 0.f;
            #pragma unroll
            for (int nt = 0; nt < 8; nt++) {
                float p0 = exp2f(s[nt][2*r]   - mn);
                float p1 = exp2f(s[nt][2*r+1] - mn);
                s[nt][2*r] = p0; s[nt][2*r+1] = p1;
                sum += p0 + p1;
            }
            sum += __shfl_xor_sync(0xffffffffu, sum, 1);
            sum += __shfl_xor_sync(0xffffffffu, sum, 2);
            l_run[r] = l_run[r]*corr + sum;
            m_run[r] = mn;
            #pragma unroll
            for (int nt = 0; nt < 4; nt++) {
                o[nt][2*r]   *= corr;
                o[nt][2*r+1] *= corr;
            }
        }

        // P -> smem as half2
        #pragma unroll
        for (int nt = 0; nt < 8; nt++) {
            int pc = nt*4 + (lane & 3);
            *(half2*)&Ps[lr*36 + pc]     = __floats2half2_rn(s[nt][0], s[nt][1]);
            *(half2*)&Ps[(lr+8)*36 + pc] = __floats2half2_rn(s[nt][2], s[nt][3]);
        }
        __syncwarp();

        // O += P @ V  (k = 64 keys via 4x k16, n = 32 dims)
        #pragma unroll
        for (int kk = 0; kk < 4; kk++) {
            unsigned af[4];
            {
                int r = wid*16 + a_r;
                ldsm4(af[0], af[1], af[2], af[3],
                      ps_u + (r*36 + kk*8 + a_ch)*4);
            }
            #pragma unroll
            for (int np = 0; np < 2; np++) {
                unsigned bv[4];
                int n = np*16 + b_nt*8 + b_r;
                ldsm4(bv[0], bv[1], bv[2], bv[3],
                      vs_u + (buf*1152 + n*36 + kk*8 + b_ch)*4);
                mma_f16(o[np*2],   af, &bv[0]);
                mma_f16(o[np*2+1], af, &bv[2]);
            }
        }
        __syncthreads();
    }

    const int b = bh / NHc, h = bh % NHc;
    const float inv0 = 1.0f / l_run[0];
    const float inv1 = 1.0f / l_run[1];
    half2* y2 = (half2*)g_y;
    #pragma unroll
    for (int nt = 0; nt < 4; nt++) {
        int pc = nt*4 + (lane & 3);           // d/2
        y2[((size_t)(b*Tc + gr0))*512 + h*16 + pc] =
            __floats2half2_rn(o[nt][0]*inv0, o[nt][1]*inv0);
        y2[((size_t)(b*Tc + gr1))*512 + h*16 + pc] =
            __floats2half2_rn(o[nt][2]*inv1, o[nt][3]*inv1);
    }
}

extern "C" void kernel_launch(void* const* d_in, const int* in_sizes, int n_in,
                              void* d_out, int out_size) {
    const float* x    = (const float*)d_in[0];
    const float* Wq   = (const float*)d_in[1];
    const float* Wk   = (const float*)d_in[2];
    const float* Wv   = (const float*)d_in[3];
    const float* Wp   = (const float*)d_in[4];
    const float* gain = (const float*)d_in[5];
    const float* cosb = (const float*)d_in[6];
    const float* sinb = (const float*)d_in[7];

    const int gemm_smem = 6 * STW * 4;                  // 61440 B
    const int attn_smem = (4608 + 2560 + 2304) * 4;     // 37888 B
    cudaFuncSetAttribute(qkv_fused, cudaFuncAttributeMaxDynamicSharedMemorySize, gemm_smem);
    cudaFuncSetAttribute(proj_gemm, cudaFuncAttributeMaxDynamicSharedMemorySize, gemm_smem);
    cudaFuncSetAttribute(attn_mma,  cudaFuncAttributeMaxDynamicSharedMemorySize, attn_smem);

    const long nprep = (long)Mc*Dc/4 + 4L*Dc*Dc/4;
    prep_half<<<(int)((nprep + 255)/256), 256>>>(x, Wq, Wk, Wv, Wp);
    qkv_fused<<<dim3(Dc/128, Mc/128, 3), 256, gemm_smem>>>(gain, cosb, sinb);
    attn_mma<<<dim3(Tc/128, Bc*NHc), 256, attn_smem>>>();
    proj_gemm<<<dim3(Dc/128, Mc/128), 256, gemm_smem>>>((float*)d_out);
}